// round 3
// baseline (speedup 1.0000x reference)
#include <cuda_runtime.h>
#include <math.h>

#define BB  64
#define LCC 512
#define LQQ 64
#define DD  256

typedef unsigned long long ull;

// packed fp32x2 helpers (Blackwell sm_103a)
__device__ __forceinline__ ull pk2(float x, float y) {
    ull r; asm("mov.b64 %0, {%1,%2};" : "=l"(r) : "f"(x), "f"(y)); return r;
}
__device__ __forceinline__ void fma2(ull& d, ull a, ull b) {
    asm("fma.rn.f32x2 %0, %1, %2, %0;" : "+l"(d) : "l"(a), "l"(b));
}
__device__ __forceinline__ float2 up2(ull v) {
    float x, y; asm("mov.b64 {%0,%1}, %2;" : "=f"(x), "=f"(y) : "l"(v));
    return make_float2(x, y);
}

// Scratch (device globals; no allocation allowed)
__device__ float g_Qp[(size_t)BB * LQQ * DD];            // wi*q + wc
__device__ float g_t[BB * LQQ];                          // <q,wq> + bias
__device__ float g_S1[(size_t)BB * LCC * LQQ];           // row-softmax(S)
__device__ float g_St[(size_t)BB * LQQ * LCC];           // S^T -> col-softmax in place
__device__ float g_C2p[2 * (size_t)BB * LQQ * DD];       // S2^T @ contex (2 K-split partials)

// ---------------------------------------------------------------------------
// K0: Q'[b,j,d] = wi[d]*q[b,j,d] + wc[d];  t[b,j] = <q[b,j], wq> + bias
// ---------------------------------------------------------------------------
__global__ void k0_prep(const float* __restrict__ q,
                        const float* __restrict__ W,
                        const float* __restrict__ bias) {
    const int bj = blockIdx.x;
    const int d  = threadIdx.x;
    const float qv = q[(size_t)bj * DD + d];
    const float wq = W[d];
    const float wc = W[DD + d];
    const float wi = W[2 * DD + d];
    g_Qp[(size_t)bj * DD + d] = fmaf(wi, qv, wc);

    float v = qv * wq;
    #pragma unroll
    for (int o = 16; o > 0; o >>= 1) v += __shfl_xor_sync(0xffffffffu, v, o);
    __shared__ float red[8];
    if ((threadIdx.x & 31) == 0) red[threadIdx.x >> 5] = v;
    __syncthreads();
    if (threadIdx.x == 0) {
        float s = 0.f;
        #pragma unroll
        for (int i = 0; i < 8; i++) s += red[i];
        g_t[bj] = s + bias[0];
    }
}

// ---------------------------------------------------------------------------
// K1: S = contex @ Q'^T + t, fused row softmax. 64x64 tile, 128 threads,
// 4x8 per thread, packed f32x2 FMAs. grid=(LC/64, B).
// Writes S1[b,i,j] and raw S^T into g_St[b,j,i].
// ---------------------------------------------------------------------------
__global__ void k1_score(const float* __restrict__ contex) {
    const int b  = blockIdx.y;
    const int i0 = blockIdx.x * 64;
    const int tid = threadIdx.x;
    const int tx = tid & 7;      // col group (8 cols each)
    const int ty = tid >> 3;     // row group (4 rows each), 0..15

    __shared__ float As[32][68];   // As[k][m] = contex[i0+m][kk+k]
    __shared__ float Bs[32][68];   // Bs[k][j] = Q'[j][kk+k]
    __shared__ float ts[64];
    if (tid < 64) ts[tid] = g_t[b * LQQ + tid];

    const float* Cb = contex + (size_t)b * LCC * DD;
    const float* Qp = g_Qp  + (size_t)b * LQQ * DD;

    ull acc[4][4];
    #pragma unroll
    for (int a = 0; a < 4; a++)
        #pragma unroll
        for (int p = 0; p < 4; p++) acc[a][p] = pk2(0.f, 0.f);

    const int lr = tid >> 1;          // 0..63
    const int lc = (tid & 1) * 16;    // 0 or 16

    for (int kk = 0; kk < DD; kk += 32) {
        #pragma unroll
        for (int u = 0; u < 4; u++) {
            const int kb = lc + u * 4;
            float4 va = *(const float4*)&Cb[(size_t)(i0 + lr) * DD + kk + kb];
            As[kb + 0][lr] = va.x; As[kb + 1][lr] = va.y;
            As[kb + 2][lr] = va.z; As[kb + 3][lr] = va.w;
            float4 vb = *(const float4*)&Qp[(size_t)lr * DD + kk + kb];
            Bs[kb + 0][lr] = vb.x; Bs[kb + 1][lr] = vb.y;
            Bs[kb + 2][lr] = vb.z; Bs[kb + 3][lr] = vb.w;
        }
        __syncthreads();
        #pragma unroll 8
        for (int k = 0; k < 32; k++) {
            float4 a4 = *(const float4*)&As[k][ty * 4];
            float4 b0 = *(const float4*)&Bs[k][tx * 8];
            float4 b1 = *(const float4*)&Bs[k][tx * 8 + 4];
            ull bp0 = pk2(b0.x, b0.y), bp1 = pk2(b0.z, b0.w);
            ull bp2 = pk2(b1.x, b1.y), bp3 = pk2(b1.z, b1.w);
            ull aa0 = pk2(a4.x, a4.x), aa1 = pk2(a4.y, a4.y);
            ull aa2 = pk2(a4.z, a4.z), aa3 = pk2(a4.w, a4.w);
            fma2(acc[0][0], aa0, bp0); fma2(acc[0][1], aa0, bp1);
            fma2(acc[0][2], aa0, bp2); fma2(acc[0][3], aa0, bp3);
            fma2(acc[1][0], aa1, bp0); fma2(acc[1][1], aa1, bp1);
            fma2(acc[1][2], aa1, bp2); fma2(acc[1][3], aa1, bp3);
            fma2(acc[2][0], aa2, bp0); fma2(acc[2][1], aa2, bp1);
            fma2(acc[2][2], aa2, bp2); fma2(acc[2][3], aa2, bp3);
            fma2(acc[3][0], aa3, bp0); fma2(acc[3][1], aa3, bp1);
            fma2(acc[3][2], aa3, bp2); fma2(acc[3][3], aa3, bp3);
        }
        __syncthreads();
    }

    // unpack, add t[j], write raw S^T, row softmax, write S1
    #pragma unroll
    for (int a = 0; a < 4; a++) {
        const int i = i0 + ty * 4 + a;
        float s[8];
        #pragma unroll
        for (int p = 0; p < 4; p++) {
            float2 f = up2(acc[a][p]);
            s[p * 2] = f.x; s[p * 2 + 1] = f.y;
        }
        #pragma unroll
        for (int c = 0; c < 8; c++) {
            const int j = tx * 8 + c;
            s[c] += ts[j];
            g_St[((size_t)b * LQQ + j) * LCC + i] = s[c];
        }
        float m = s[0];
        #pragma unroll
        for (int c = 1; c < 8; c++) m = fmaxf(m, s[c]);
        #pragma unroll
        for (int o = 1; o < 8; o <<= 1) m = fmaxf(m, __shfl_xor_sync(0xffffffffu, m, o));
        float e[8], sum = 0.f;
        #pragma unroll
        for (int c = 0; c < 8; c++) { e[c] = expf(s[c] - m); sum += e[c]; }
        #pragma unroll
        for (int o = 1; o < 8; o <<= 1) sum += __shfl_xor_sync(0xffffffffu, sum, o);
        const float inv = 1.f / sum;
        float4 o0 = make_float4(e[0] * inv, e[1] * inv, e[2] * inv, e[3] * inv);
        float4 o1 = make_float4(e[4] * inv, e[5] * inv, e[6] * inv, e[7] * inv);
        *(float4*)&g_S1[((size_t)b * LCC + i) * LQQ + tx * 8]     = o0;
        *(float4*)&g_S1[((size_t)b * LCC + i) * LQQ + tx * 8 + 4] = o1;
    }
}

// ---------------------------------------------------------------------------
// K2: column softmax (length 512) in place on g_St rows.
// ---------------------------------------------------------------------------
__global__ void k2_colsm() {
    const int bj = blockIdx.x;
    float* row = g_St + (size_t)bj * LCC;
    const int tid = threadIdx.x;
    float v0 = row[tid], v1 = row[tid + 256];

    __shared__ float red[8];
    float m = fmaxf(v0, v1);
    #pragma unroll
    for (int o = 16; o > 0; o >>= 1) m = fmaxf(m, __shfl_xor_sync(0xffffffffu, m, o));
    if ((tid & 31) == 0) red[tid >> 5] = m;
    __syncthreads();
    m = fmaxf(fmaxf(fmaxf(red[0], red[1]), fmaxf(red[2], red[3])),
              fmaxf(fmaxf(red[4], red[5]), fmaxf(red[6], red[7])));
    __syncthreads();

    float e0 = expf(v0 - m), e1 = expf(v1 - m);
    float s = e0 + e1;
    #pragma unroll
    for (int o = 16; o > 0; o >>= 1) s += __shfl_xor_sync(0xffffffffu, s, o);
    if ((tid & 31) == 0) red[tid >> 5] = s;
    __syncthreads();
    s = red[0] + red[1] + red[2] + red[3] + red[4] + red[5] + red[6] + red[7];
    const float inv = 1.f / s;
    row[tid]       = e0 * inv;
    row[tid + 256] = e1 * inv;
}

// ---------------------------------------------------------------------------
// K3: C2 = S2^T @ contex, K split in 2 across blockIdx.z into partials.
// 64x64 tile (j x n), 128 threads, 4x8/thread, f32x2.
// grid = (D/64, B, 2)
// ---------------------------------------------------------------------------
__global__ void k3_c2(const float* __restrict__ contex) {
    const int b  = blockIdx.y;
    const int n0 = blockIdx.x * 64;
    const int kk0 = blockIdx.z * 256;
    const int tid = threadIdx.x;
    const int tx = tid & 7, ty = tid >> 3;

    __shared__ float As[32][68];   // As[k][j] = S2t[j][kk+k]
    __shared__ float Bs[32][68];   // Bs[k][n] = contex[kk+k][n0+n]

    const float* S2t = g_St + (size_t)b * LQQ * LCC;
    const float* Cb  = contex + (size_t)b * LCC * DD;

    ull acc[4][4];
    #pragma unroll
    for (int a = 0; a < 4; a++)
        #pragma unroll
        for (int p = 0; p < 4; p++) acc[a][p] = pk2(0.f, 0.f);

    const int lr = tid >> 1;          // A: row j 0..63
    const int lc = (tid & 1) * 16;    // A: k offset
    const int kr = tid >> 2;          // B: k row 0..31
    const int nc = (tid & 3) * 16;    // B: n offset

    for (int kk = kk0; kk < kk0 + 256; kk += 32) {
        #pragma unroll
        for (int u = 0; u < 4; u++) {
            const int kb = lc + u * 4;
            float4 va = *(const float4*)&S2t[(size_t)lr * LCC + kk + kb];
            As[kb + 0][lr] = va.x; As[kb + 1][lr] = va.y;
            As[kb + 2][lr] = va.z; As[kb + 3][lr] = va.w;
            *(float4*)&Bs[kr][nc + u * 4] =
                *(const float4*)&Cb[(size_t)(kk + kr) * DD + n0 + nc + u * 4];
        }
        __syncthreads();
        #pragma unroll 8
        for (int k = 0; k < 32; k++) {
            float4 a4 = *(const float4*)&As[k][ty * 4];
            float4 b0 = *(const float4*)&Bs[k][tx * 8];
            float4 b1 = *(const float4*)&Bs[k][tx * 8 + 4];
            ull bp0 = pk2(b0.x, b0.y), bp1 = pk2(b0.z, b0.w);
            ull bp2 = pk2(b1.x, b1.y), bp3 = pk2(b1.z, b1.w);
            ull aa0 = pk2(a4.x, a4.x), aa1 = pk2(a4.y, a4.y);
            ull aa2 = pk2(a4.z, a4.z), aa3 = pk2(a4.w, a4.w);
            fma2(acc[0][0], aa0, bp0); fma2(acc[0][1], aa0, bp1);
            fma2(acc[0][2], aa0, bp2); fma2(acc[0][3], aa0, bp3);
            fma2(acc[1][0], aa1, bp0); fma2(acc[1][1], aa1, bp1);
            fma2(acc[1][2], aa1, bp2); fma2(acc[1][3], aa1, bp3);
            fma2(acc[2][0], aa2, bp0); fma2(acc[2][1], aa2, bp1);
            fma2(acc[2][2], aa2, bp2); fma2(acc[2][3], aa2, bp3);
            fma2(acc[3][0], aa3, bp0); fma2(acc[3][1], aa3, bp1);
            fma2(acc[3][2], aa3, bp2); fma2(acc[3][3], aa3, bp3);
        }
        __syncthreads();
    }

    float* outp = g_C2p + (size_t)blockIdx.z * BB * LQQ * DD;
    #pragma unroll
    for (int a = 0; a < 4; a++) {
        const int j = ty * 4 + a;
        float2 f0 = up2(acc[a][0]), f1 = up2(acc[a][1]);
        float2 f2 = up2(acc[a][2]), f3 = up2(acc[a][3]);
        float4 o0 = make_float4(f0.x, f0.y, f1.x, f1.y);
        float4 o1 = make_float4(f2.x, f2.y, f3.x, f3.y);
        *(float4*)&outp[((size_t)b * LQQ + j) * DD + n0 + tx * 8]     = o0;
        *(float4*)&outp[((size_t)b * LQQ + j) * DD + n0 + tx * 8 + 4] = o1;
    }
}

// ---------------------------------------------------------------------------
// K4: A = S1 @ question, Bm = S1 @ C2 (K=64), fused output assembly.
// 64x64 tile, 128 threads, 4x8/thread, f32x2. 8 N-chunks of 64.
// out[b,i] = [contex | A | contex*A | contex*Bm]
// ---------------------------------------------------------------------------
__global__ void k4_out(const float* __restrict__ contex,
                       const float* __restrict__ question,
                       float* __restrict__ out) {
    const int b  = blockIdx.y;
    const int i0 = blockIdx.x * 64;
    const int tid = threadIdx.x;
    const int tx = tid & 7, ty = tid >> 3;

    __shared__ float As[64][68];   // As[k=j][i] = S1[i0+i][j]
    __shared__ float Bs[64][68];   // B tile; reused for contex tile in epilogue

    const float* S1b = g_S1 + (size_t)b * LCC * LQQ;
    {
        const int lr = tid >> 1;          // i 0..63
        const int jc = (tid & 1) * 32;    // j offset
        #pragma unroll
        for (int u = 0; u < 8; u++) {
            const int jb = jc + u * 4;
            float4 v = *(const float4*)&S1b[(size_t)(i0 + lr) * LQQ + jb];
            As[jb + 0][lr] = v.x; As[jb + 1][lr] = v.y;
            As[jb + 2][lr] = v.z; As[jb + 3][lr] = v.w;
        }
    }

    const float* Cb  = contex   + (size_t)b * LCC * DD;
    const float* Qb  = question + (size_t)b * LQQ * DD;
    const float* C2a = g_C2p    + (size_t)b * LQQ * DD;
    const float* C2b = g_C2p + (size_t)BB * LQQ * DD + (size_t)b * LQQ * DD;
    float* outb = out + (size_t)b * LCC * 1024;

    const int jr = tid >> 1;          // B load: row j 0..63
    const int ncb = (tid & 1) * 32;   // B load: col offset

    for (int chunk = 0; chunk < 8; chunk++) {
        const int c0 = (chunk < 4) ? chunk * 64 : (chunk - 4) * 64;
        __syncthreads();   // As ready (first iter) / Bs safe to overwrite
        if (chunk < 4) {
            #pragma unroll
            for (int u = 0; u < 8; u++)
                *(float4*)&Bs[jr][ncb + u * 4] =
                    *(const float4*)&Qb[(size_t)jr * DD + c0 + ncb + u * 4];
        } else {
            #pragma unroll
            for (int u = 0; u < 8; u++) {
                float4 x = *(const float4*)&C2a[(size_t)jr * DD + c0 + ncb + u * 4];
                float4 y = *(const float4*)&C2b[(size_t)jr * DD + c0 + ncb + u * 4];
                *(float4*)&Bs[jr][ncb + u * 4] =
                    make_float4(x.x + y.x, x.y + y.y, x.z + y.z, x.w + y.w);
            }
        }
        __syncthreads();

        ull acc[4][4];
        #pragma unroll
        for (int a = 0; a < 4; a++)
            #pragma unroll
            for (int p = 0; p < 4; p++) acc[a][p] = pk2(0.f, 0.f);

        #pragma unroll 8
        for (int k = 0; k < 64; k++) {
            float4 a4 = *(const float4*)&As[k][ty * 4];
            float4 b0 = *(const float4*)&Bs[k][tx * 8];
            float4 b1 = *(const float4*)&Bs[k][tx * 8 + 4];
            ull bp0 = pk2(b0.x, b0.y), bp1 = pk2(b0.z, b0.w);
            ull bp2 = pk2(b1.x, b1.y), bp3 = pk2(b1.z, b1.w);
            ull aa0 = pk2(a4.x, a4.x), aa1 = pk2(a4.y, a4.y);
            ull aa2 = pk2(a4.z, a4.z), aa3 = pk2(a4.w, a4.w);
            fma2(acc[0][0], aa0, bp0); fma2(acc[0][1], aa0, bp1);
            fma2(acc[0][2], aa0, bp2); fma2(acc[0][3], aa0, bp3);
            fma2(acc[1][0], aa1, bp0); fma2(acc[1][1], aa1, bp1);
            fma2(acc[1][2], aa1, bp2); fma2(acc[1][3], aa1, bp3);
            fma2(acc[2][0], aa2, bp0); fma2(acc[2][1], aa2, bp1);
            fma2(acc[2][2], aa2, bp2); fma2(acc[2][3], aa2, bp3);
            fma2(acc[3][0], aa3, bp0); fma2(acc[3][1], aa3, bp1);
            fma2(acc[3][2], aa3, bp2); fma2(acc[3][3], aa3, bp3);
        }
        __syncthreads();

        // load contex tile into Bs for epilogue (rows i, cols c0..c0+63)
        #pragma unroll
        for (int u = 0; u < 8; u++)
            *(float4*)&Bs[jr][ncb + u * 4] =
                *(const float4*)&Cb[(size_t)(i0 + jr) * DD + c0 + ncb + u * 4];
        __syncthreads();

        #pragma unroll
        for (int a = 0; a < 4; a++) {
            const int i = i0 + ty * 4 + a;
            float2 f0 = up2(acc[a][0]), f1 = up2(acc[a][1]);
            float2 f2 = up2(acc[a][2]), f3 = up2(acc[a][3]);
            float4 acc0 = make_float4(f0.x, f0.y, f1.x, f1.y);
            float4 acc1 = make_float4(f2.x, f2.y, f3.x, f3.y);
            float4 c0v = *(const float4*)&Bs[ty * 4 + a][tx * 8];
            float4 c1v = *(const float4*)&Bs[ty * 4 + a][tx * 8 + 4];
            float4 p0 = make_float4(c0v.x * acc0.x, c0v.y * acc0.y,
                                    c0v.z * acc0.z, c0v.w * acc0.w);
            float4 p1 = make_float4(c1v.x * acc1.x, c1v.y * acc1.y,
                                    c1v.z * acc1.z, c1v.w * acc1.w);
            float* orow = outb + (size_t)i * 1024;
            const int col = c0 + tx * 8;
            if (chunk < 4) {
                *(float4*)&orow[col]           = c0v;   // contex
                *(float4*)&orow[col + 4]       = c1v;
                *(float4*)&orow[256 + col]     = acc0;  // A
                *(float4*)&orow[256 + col + 4] = acc1;
                *(float4*)&orow[512 + col]     = p0;    // contex * A
                *(float4*)&orow[512 + col + 4] = p1;
            } else {
                *(float4*)&orow[768 + col]     = p0;    // contex * Bm
                *(float4*)&orow[768 + col + 4] = p1;
            }
        }
    }
}

// ---------------------------------------------------------------------------
extern "C" void kernel_launch(void* const* d_in, const int* in_sizes, int n_in,
                              void* d_out, int out_size) {
    const float* contex   = (const float*)d_in[0];
    const float* question = (const float*)d_in[1];
    const float* W        = (const float*)d_in[2];
    const float* bias     = (const float*)d_in[3];
    float* out = (float*)d_out;

    k0_prep<<<BB * LQQ, 256>>>(question, W, bias);
    k1_score<<<dim3(LCC / 64, BB), 128>>>(contex);
    k2_colsm<<<BB * LQQ, 256>>>();
    k3_c2<<<dim3(DD / 64, BB, 2), 128>>>(contex);
    k4_out<<<dim3(LCC / 64, BB), 128>>>(contex, question, out);
}

// round 4
// speedup vs baseline: 1.9722x; 1.9722x over previous
#include <cuda_runtime.h>
#include <math.h>

#define BB  64
#define LCC 512
#define LQQ 64
#define DD  256

// ---------------------------------------------------------------------------
// tf32 mma helpers (m16n8k8, row.col, fp32 accum)
// ---------------------------------------------------------------------------
__device__ __forceinline__ unsigned tf32c(float x) {
    unsigned r; asm("cvt.rna.tf32.f32 %0, %1;" : "=r"(r) : "f"(x)); return r;
}
__device__ __forceinline__ void mma8(float& d0, float& d1, float& d2, float& d3,
                                     unsigned a0, unsigned a1, unsigned a2, unsigned a3,
                                     unsigned b0, unsigned b1) {
    asm("mma.sync.aligned.m16n8k8.row.col.f32.tf32.tf32.f32 "
        "{%0,%1,%2,%3},{%4,%5,%6,%7},{%8,%9},{%0,%1,%2,%3};"
        : "+f"(d0), "+f"(d1), "+f"(d2), "+f"(d3)
        : "r"(a0), "r"(a1), "r"(a2), "r"(a3), "r"(b0), "r"(b1));
}

// Scratch (device globals; no allocation allowed)
__device__ float g_Qp[(size_t)BB * LQQ * DD];            // wi*q + wc
__device__ float g_t[BB * LQQ];                          // <q,wq> + bias
__device__ float g_S1[(size_t)BB * LCC * LQQ];           // row-softmax(S)
__device__ float g_St[(size_t)BB * LQQ * LCC];           // S^T -> col-softmax in place
__device__ float g_C2p[2 * (size_t)BB * LQQ * DD];       // S2^T @ contex (2 K-split partials)

// ---------------------------------------------------------------------------
// K0: Q'[b,j,d] = wi[d]*q[b,j,d] + wc[d];  t[b,j] = <q[b,j], wq> + bias
// ---------------------------------------------------------------------------
__global__ void k0_prep(const float* __restrict__ q,
                        const float* __restrict__ W,
                        const float* __restrict__ bias) {
    const int bj = blockIdx.x;
    const int d  = threadIdx.x;
    const float qv = q[(size_t)bj * DD + d];
    const float wq = W[d];
    const float wc = W[DD + d];
    const float wi = W[2 * DD + d];
    g_Qp[(size_t)bj * DD + d] = fmaf(wi, qv, wc);

    float v = qv * wq;
    #pragma unroll
    for (int o = 16; o > 0; o >>= 1) v += __shfl_xor_sync(0xffffffffu, v, o);
    __shared__ float red[8];
    if ((threadIdx.x & 31) == 0) red[threadIdx.x >> 5] = v;
    __syncthreads();
    if (threadIdx.x == 0) {
        float s = 0.f;
        #pragma unroll
        for (int i = 0; i < 8; i++) s += red[i];
        g_t[bj] = s + bias[0];
    }
}

// ---------------------------------------------------------------------------
// K1: S = contex @ Q'^T + t via tf32 mma, fused row softmax.
// Block tile 128(i) x 64(j), 128 threads = 4 warps (each 32x64), K=256.
// Writes S1[b,i,j] and raw S^T into g_St[b,j,i].  grid=(4, B)
// ---------------------------------------------------------------------------
__global__ void __launch_bounds__(128) k1_score(const float* __restrict__ contex) {
    const int b  = blockIdx.y;
    const int i0 = blockIdx.x * 128;
    const int tid = threadIdx.x;
    const int warp = tid >> 5, lane = tid & 31;
    const int g = lane >> 2, t = lane & 3;
    const int wm = warp * 32;

    __shared__ float As[128][36];   // contex tile [m][k], stride 36 (==4 mod 32)
    __shared__ float Bs[64][36];    // Q' tile [n][k], stride 36
    __shared__ float ts[64];
    if (tid < 64) ts[tid] = g_t[b * LQQ + tid];

    const float* Cb = contex + (size_t)b * LCC * DD;
    const float* Qp = g_Qp  + (size_t)b * LQQ * DD;

    float acc[2][8][4];
    #pragma unroll
    for (int mt = 0; mt < 2; mt++)
        #pragma unroll
        for (int nt = 0; nt < 8; nt++)
            #pragma unroll
            for (int r = 0; r < 4; r++) acc[mt][nt][r] = 0.f;

    for (int kk = 0; kk < DD; kk += 32) {
        __syncthreads();
        {   // fill A: 128 rows x 32 k  (one row per thread)
            const float* src = &Cb[(size_t)(i0 + tid) * DD + kk];
            unsigned* dst = (unsigned*)&As[tid][0];
            #pragma unroll
            for (int u = 0; u < 8; u++) {
                float4 v = *(const float4*)&src[u * 4];
                dst[u * 4 + 0] = tf32c(v.x); dst[u * 4 + 1] = tf32c(v.y);
                dst[u * 4 + 2] = tf32c(v.z); dst[u * 4 + 3] = tf32c(v.w);
            }
        }
        {   // fill B: 64 rows x 32 k (half-row per thread)
            const int jr = tid & 63, ko = (tid >> 6) * 16;
            const float* src = &Qp[(size_t)jr * DD + kk + ko];
            unsigned* dst = (unsigned*)&Bs[jr][ko];
            #pragma unroll
            for (int u = 0; u < 4; u++) {
                float4 v = *(const float4*)&src[u * 4];
                dst[u * 4 + 0] = tf32c(v.x); dst[u * 4 + 1] = tf32c(v.y);
                dst[u * 4 + 2] = tf32c(v.z); dst[u * 4 + 3] = tf32c(v.w);
            }
        }
        __syncthreads();
        #pragma unroll
        for (int kc = 0; kc < 32; kc += 8) {
            unsigned a[2][4];
            #pragma unroll
            for (int mt = 0; mt < 2; mt++) {
                const int r = wm + mt * 16 + g;
                a[mt][0] = *(const unsigned*)&As[r][kc + t];
                a[mt][1] = *(const unsigned*)&As[r + 8][kc + t];
                a[mt][2] = *(const unsigned*)&As[r][kc + t + 4];
                a[mt][3] = *(const unsigned*)&As[r + 8][kc + t + 4];
            }
            #pragma unroll
            for (int nt = 0; nt < 8; nt++) {
                const int n = nt * 8 + g;
                unsigned b0 = *(const unsigned*)&Bs[n][kc + t];
                unsigned b1 = *(const unsigned*)&Bs[n][kc + t + 4];
                mma8(acc[0][nt][0], acc[0][nt][1], acc[0][nt][2], acc[0][nt][3],
                     a[0][0], a[0][1], a[0][2], a[0][3], b0, b1);
                mma8(acc[1][nt][0], acc[1][nt][1], acc[1][nt][2], acc[1][nt][3],
                     a[1][0], a[1][1], a[1][2], a[1][3], b0, b1);
            }
        }
    }

    // epilogue: +t[j], raw S^T out, row softmax -> S1
    float* Stb = g_St + (size_t)b * LQQ * LCC;
    float* S1b = g_S1 + (size_t)b * LCC * LQQ;
    #pragma unroll
    for (int mt = 0; mt < 2; mt++)
        #pragma unroll
        for (int h = 0; h < 2; h++) {
            const int i = i0 + wm + mt * 16 + h * 8 + g;
            float s[16];
            #pragma unroll
            for (int nt = 0; nt < 8; nt++) {
                s[2 * nt]     = acc[mt][nt][2 * h]     + ts[nt * 8 + 2 * t];
                s[2 * nt + 1] = acc[mt][nt][2 * h + 1] + ts[nt * 8 + 2 * t + 1];
            }
            #pragma unroll
            for (int nt = 0; nt < 8; nt++) {
                Stb[(size_t)(nt * 8 + 2 * t) * LCC + i]     = s[2 * nt];
                Stb[(size_t)(nt * 8 + 2 * t + 1) * LCC + i] = s[2 * nt + 1];
            }
            float m = s[0];
            #pragma unroll
            for (int c = 1; c < 16; c++) m = fmaxf(m, s[c]);
            m = fmaxf(m, __shfl_xor_sync(0xffffffffu, m, 1));
            m = fmaxf(m, __shfl_xor_sync(0xffffffffu, m, 2));
            float e[16], sum = 0.f;
            #pragma unroll
            for (int c = 0; c < 16; c++) { e[c] = expf(s[c] - m); sum += e[c]; }
            sum += __shfl_xor_sync(0xffffffffu, sum, 1);
            sum += __shfl_xor_sync(0xffffffffu, sum, 2);
            const float inv = 1.f / sum;
            #pragma unroll
            for (int nt = 0; nt < 8; nt++) {
                float2 o = make_float2(e[2 * nt] * inv, e[2 * nt + 1] * inv);
                *(float2*)&S1b[(size_t)i * LQQ + nt * 8 + 2 * t] = o;
            }
        }
}

// ---------------------------------------------------------------------------
// K2: column softmax (length 512) in place on g_St rows.
// ---------------------------------------------------------------------------
__global__ void k2_colsm() {
    const int bj = blockIdx.x;
    float* row = g_St + (size_t)bj * LCC;
    const int tid = threadIdx.x;
    float v0 = row[tid], v1 = row[tid + 256];

    __shared__ float red[8];
    float m = fmaxf(v0, v1);
    #pragma unroll
    for (int o = 16; o > 0; o >>= 1) m = fmaxf(m, __shfl_xor_sync(0xffffffffu, m, o));
    if ((tid & 31) == 0) red[tid >> 5] = m;
    __syncthreads();
    m = fmaxf(fmaxf(fmaxf(red[0], red[1]), fmaxf(red[2], red[3])),
              fmaxf(fmaxf(red[4], red[5]), fmaxf(red[6], red[7])));
    __syncthreads();

    float e0 = expf(v0 - m), e1 = expf(v1 - m);
    float s = e0 + e1;
    #pragma unroll
    for (int o = 16; o > 0; o >>= 1) s += __shfl_xor_sync(0xffffffffu, s, o);
    if ((tid & 31) == 0) red[tid >> 5] = s;
    __syncthreads();
    s = red[0] + red[1] + red[2] + red[3] + red[4] + red[5] + red[6] + red[7];
    const float inv = 1.f / s;
    row[tid]       = e0 * inv;
    row[tid + 256] = e1 * inv;
}

// ---------------------------------------------------------------------------
// K3: C2 = S2^T @ contex via tf32 mma. Block tile 64(j) x 128(d), K split 2.
// 128 threads = 4 warps in 2x2 (each 32x64).  grid=(2, B, 2)
// ---------------------------------------------------------------------------
__global__ void __launch_bounds__(128) k3_c2(const float* __restrict__ contex) {
    const int b   = blockIdx.y;
    const int n0  = blockIdx.x * 128;
    const int kk0 = blockIdx.z * 256;
    const int tid = threadIdx.x;
    const int warp = tid >> 5, lane = tid & 31;
    const int g = lane >> 2, t = lane & 3;
    const int wm = (warp & 1) * 32;
    const int wn = (warp >> 1) * 64;

    __shared__ float As[64][36];    // S2t tile [j][k], stride 36 (==4 mod 32)
    __shared__ float Bs[32][136];   // contex tile [k][n], stride 136 (==8 mod 32)

    const float* S2t = g_St + (size_t)b * LQQ * LCC;
    const float* Cb  = contex + (size_t)b * LCC * DD;

    float acc[2][8][4];
    #pragma unroll
    for (int mt = 0; mt < 2; mt++)
        #pragma unroll
        for (int nt = 0; nt < 8; nt++)
            #pragma unroll
            for (int r = 0; r < 4; r++) acc[mt][nt][r] = 0.f;

    for (int kk = kk0; kk < kk0 + 256; kk += 32) {
        __syncthreads();
        {   // fill A: 64 rows x 32 k
            const int jr = tid & 63, ko = (tid >> 6) * 16;
            const float* src = &S2t[(size_t)jr * LCC + kk + ko];
            unsigned* dst = (unsigned*)&As[jr][ko];
            #pragma unroll
            for (int u = 0; u < 4; u++) {
                float4 v = *(const float4*)&src[u * 4];
                dst[u * 4 + 0] = tf32c(v.x); dst[u * 4 + 1] = tf32c(v.y);
                dst[u * 4 + 2] = tf32c(v.z); dst[u * 4 + 3] = tf32c(v.w);
            }
        }
        {   // fill B: 32 k-rows x 128 n
            const int kr = tid >> 2, nc = (tid & 3) * 32;
            const float* src = &Cb[(size_t)(kk + kr) * DD + n0 + nc];
            unsigned* dst = (unsigned*)&Bs[kr][nc];
            #pragma unroll
            for (int u = 0; u < 8; u++) {
                float4 v = *(const float4*)&src[u * 4];
                dst[u * 4 + 0] = tf32c(v.x); dst[u * 4 + 1] = tf32c(v.y);
                dst[u * 4 + 2] = tf32c(v.z); dst[u * 4 + 3] = tf32c(v.w);
            }
        }
        __syncthreads();
        #pragma unroll
        for (int kc = 0; kc < 32; kc += 8) {
            unsigned a[2][4];
            #pragma unroll
            for (int mt = 0; mt < 2; mt++) {
                const int r = wm + mt * 16 + g;
                a[mt][0] = *(const unsigned*)&As[r][kc + t];
                a[mt][1] = *(const unsigned*)&As[r + 8][kc + t];
                a[mt][2] = *(const unsigned*)&As[r][kc + t + 4];
                a[mt][3] = *(const unsigned*)&As[r + 8][kc + t + 4];
            }
            #pragma unroll
            for (int nt = 0; nt < 8; nt++) {
                const int n = wn + nt * 8 + g;
                unsigned b0 = *(const unsigned*)&Bs[kc + t][n];
                unsigned b1 = *(const unsigned*)&Bs[kc + t + 4][n];
                mma8(acc[0][nt][0], acc[0][nt][1], acc[0][nt][2], acc[0][nt][3],
                     a[0][0], a[0][1], a[0][2], a[0][3], b0, b1);
                mma8(acc[1][nt][0], acc[1][nt][1], acc[1][nt][2], acc[1][nt][3],
                     a[1][0], a[1][1], a[1][2], a[1][3], b0, b1);
            }
        }
    }

    float* outp = g_C2p + (size_t)blockIdx.z * BB * LQQ * DD + (size_t)b * LQQ * DD;
    #pragma unroll
    for (int mt = 0; mt < 2; mt++)
        #pragma unroll
        for (int h = 0; h < 2; h++) {
            const int j = wm + mt * 16 + h * 8 + g;
            #pragma unroll
            for (int nt = 0; nt < 8; nt++) {
                float2 o = make_float2(acc[mt][nt][2 * h], acc[mt][nt][2 * h + 1]);
                *(float2*)&outp[(size_t)j * DD + n0 + wn + nt * 8 + 2 * t] = o;
            }
        }
}

// ---------------------------------------------------------------------------
// K4: A = S1 @ question, Bm = S1 @ (C2p0+C2p1) via tf32 mma (K=64),
// fused output assembly: out[b,i] = [contex | A | contex*A | contex*Bm]
// Block tile 128(i) x 64 per chunk, 8 chunks. 128 threads = 4 warps (32x64).
// grid=(4, B). Dynamic smem.
// ---------------------------------------------------------------------------
__global__ void __launch_bounds__(128) k4_out(const float* __restrict__ contex,
                                              const float* __restrict__ question,
                                              float* __restrict__ out) {
    const int b  = blockIdx.y;
    const int i0 = blockIdx.x * 128;
    const int tid = threadIdx.x;
    const int warp = tid >> 5, lane = tid & 31;
    const int g = lane >> 2, t = lane & 3;
    const int wm = warp * 32;

    extern __shared__ float sm4[];
    float (*As)[68] = (float(*)[68])sm4;                 // S1 tile [i][j], 128x68
    float (*Bs)[72] = (float(*)[72])(sm4 + 128 * 68);    // B tile [k=j][n], 64x72

    const float* S1b = g_S1 + (size_t)b * LCC * LQQ;
    {   // fill A once: one S1 row per thread, cvt to tf32
        const float* src = &S1b[(size_t)(i0 + tid) * LQQ];
        unsigned* dst = (unsigned*)&As[tid][0];
        #pragma unroll
        for (int u = 0; u < 16; u++) {
            float4 v = *(const float4*)&src[u * 4];
            dst[u * 4 + 0] = tf32c(v.x); dst[u * 4 + 1] = tf32c(v.y);
            dst[u * 4 + 2] = tf32c(v.z); dst[u * 4 + 3] = tf32c(v.w);
        }
    }

    const float* Cb = contex   + (size_t)b * LCC * DD;
    const float* Qb = question + (size_t)b * LQQ * DD;
    const float* P0 = g_C2p    + (size_t)b * LQQ * DD;
    const float* P1 = g_C2p + (size_t)BB * LQQ * DD + (size_t)b * LQQ * DD;
    float* outb = out + (size_t)b * LCC * 1024;

    for (int chunk = 0; chunk < 8; chunk++) {
        const int c0 = (chunk & 3) * 64;
        __syncthreads();
        {   // fill B chunk: question or summed C2 partials
            const int jr = tid & 63, off = (tid >> 6) * 32;
            unsigned* dst = (unsigned*)&Bs[jr][off];
            if (chunk < 4) {
                const float* src = &Qb[(size_t)jr * DD + c0 + off];
                #pragma unroll
                for (int u = 0; u < 8; u++) {
                    float4 v = *(const float4*)&src[u * 4];
                    dst[u * 4 + 0] = tf32c(v.x); dst[u * 4 + 1] = tf32c(v.y);
                    dst[u * 4 + 2] = tf32c(v.z); dst[u * 4 + 3] = tf32c(v.w);
                }
            } else {
                const float* s0 = &P0[(size_t)jr * DD + c0 + off];
                const float* s1 = &P1[(size_t)jr * DD + c0 + off];
                #pragma unroll
                for (int u = 0; u < 8; u++) {
                    float4 x = *(const float4*)&s0[u * 4];
                    float4 y = *(const float4*)&s1[u * 4];
                    dst[u * 4 + 0] = tf32c(x.x + y.x); dst[u * 4 + 1] = tf32c(x.y + y.y);
                    dst[u * 4 + 2] = tf32c(x.z + y.z); dst[u * 4 + 3] = tf32c(x.w + y.w);
                }
            }
        }
        __syncthreads();

        float acc[2][8][4];
        #pragma unroll
        for (int mt = 0; mt < 2; mt++)
            #pragma unroll
            for (int nt = 0; nt < 8; nt++)
                #pragma unroll
                for (int r = 0; r < 4; r++) acc[mt][nt][r] = 0.f;

        #pragma unroll
        for (int kc = 0; kc < 64; kc += 8) {
            unsigned a[2][4];
            #pragma unroll
            for (int mt = 0; mt < 2; mt++) {
                const int r = wm + mt * 16 + g;
                a[mt][0] = *(const unsigned*)&As[r][kc + t];
                a[mt][1] = *(const unsigned*)&As[r + 8][kc + t];
                a[mt][2] = *(const unsigned*)&As[r][kc + t + 4];
                a[mt][3] = *(const unsigned*)&As[r + 8][kc + t + 4];
            }
            #pragma unroll
            for (int nt = 0; nt < 8; nt++) {
                const int n = nt * 8 + g;
                unsigned b0 = *(const unsigned*)&Bs[kc + t][n];
                unsigned b1 = *(const unsigned*)&Bs[kc + t + 4][n];
                mma8(acc[0][nt][0], acc[0][nt][1], acc[0][nt][2], acc[0][nt][3],
                     a[0][0], a[0][1], a[0][2], a[0][3], b0, b1);
                mma8(acc[1][nt][0], acc[1][nt][1], acc[1][nt][2], acc[1][nt][3],
                     a[1][0], a[1][1], a[1][2], a[1][3], b0, b1);
            }
        }

        // epilogue: contex straight from gmem (L2-resident), assemble output
        #pragma unroll
        for (int mt = 0; mt < 2; mt++)
            #pragma unroll
            for (int h = 0; h < 2; h++) {
                const int i = i0 + wm + mt * 16 + h * 8 + g;
                const float* crow = &Cb[(size_t)i * DD];
                float* orow = &outb[(size_t)i * 1024];
                #pragma unroll
                for (int nt = 0; nt < 8; nt++) {
                    const int col = c0 + nt * 8 + 2 * t;
                    float2 cv = *(const float2*)&crow[col];
                    float2 av = make_float2(acc[mt][nt][2 * h], acc[mt][nt][2 * h + 1]);
                    float2 pv = make_float2(cv.x * av.x, cv.y * av.y);
                    if (chunk < 4) {
                        *(float2*)&orow[col]       = cv;   // contex
                        *(float2*)&orow[256 + col] = av;   // A
                        *(float2*)&orow[512 + col] = pv;   // contex * A
                    } else {
                        *(float2*)&orow[768 + col] = pv;   // contex * Bm
                    }
                }
            }
    }
}

// ---------------------------------------------------------------------------
extern "C" void kernel_launch(void* const* d_in, const int* in_sizes, int n_in,
                              void* d_out, int out_size) {
    const float* contex   = (const float*)d_in[0];
    const float* question = (const float*)d_in[1];
    const float* W        = (const float*)d_in[2];
    const float* bias     = (const float*)d_in[3];
    float* out = (float*)d_out;

    const int k4smem = (128 * 68 + 64 * 72) * (int)sizeof(float);   // 53248 B
    cudaFuncSetAttribute(k4_out, cudaFuncAttributeMaxDynamicSharedMemorySize, k4smem);

    k0_prep<<<BB * LQQ, 256>>>(question, W, bias);
    k1_score<<<dim3(4, BB), 128>>>(contex);
    k2_colsm<<<BB * LQQ, 256>>>();
    k3_c2<<<dim3(2, BB, 2), 128>>>(contex);
    k4_out<<<dim3(4, BB), 128, k4smem>>>(contex, question, out);
}

// round 5
// speedup vs baseline: 2.3409x; 1.1870x over previous
#include <cuda_runtime.h>
#include <math.h>

#define BB  64
#define LCC 512
#define LQQ 64
#define DD  256

// ---------------------------------------------------------------------------
// tf32 mma helpers (m16n8k8, row.col, fp32 accum)
// ---------------------------------------------------------------------------
__device__ __forceinline__ unsigned tf32c(float x) {
    unsigned r; asm("cvt.rna.tf32.f32 %0, %1;" : "=r"(r) : "f"(x)); return r;
}
__device__ __forceinline__ void mma8(float& d0, float& d1, float& d2, float& d3,
                                     unsigned a0, unsigned a1, unsigned a2, unsigned a3,
                                     unsigned b0, unsigned b1) {
    asm("mma.sync.aligned.m16n8k8.row.col.f32.tf32.tf32.f32 "
        "{%0,%1,%2,%3},{%4,%5,%6,%7},{%8,%9},{%0,%1,%2,%3};"
        : "+f"(d0), "+f"(d1), "+f"(d2), "+f"(d3)
        : "r"(a0), "r"(a1), "r"(a2), "r"(a3), "r"(b0), "r"(b1));
}
__device__ __forceinline__ void cvst4(unsigned* dst, float4 v) {
    dst[0] = tf32c(v.x); dst[1] = tf32c(v.y); dst[2] = tf32c(v.z); dst[3] = tf32c(v.w);
}

// Scratch (device globals; no allocation allowed)
__device__ float g_Qp[(size_t)BB * LQQ * DD];            // wi*q + wc
__device__ float g_t[BB * LQQ];                          // <q,wq> + bias
__device__ float g_S1[(size_t)BB * LCC * LQQ];           // row-softmax(S)
__device__ float g_St[(size_t)BB * LQQ * LCC];           // S^T -> col-softmax in place
__device__ float g_C2p[2 * (size_t)BB * LQQ * DD];       // S2^T @ contex (2 K-split partials)

// ---------------------------------------------------------------------------
// K0: Q'[b,j,d] = wi[d]*q[b,j,d] + wc[d];  t[b,j] = <q[b,j], wq> + bias
// ---------------------------------------------------------------------------
__global__ void k0_prep(const float* __restrict__ q,
                        const float* __restrict__ W,
                        const float* __restrict__ bias) {
    const int bj = blockIdx.x;
    const int d  = threadIdx.x;
    const float qv = q[(size_t)bj * DD + d];
    const float wq = W[d];
    const float wc = W[DD + d];
    const float wi = W[2 * DD + d];
    g_Qp[(size_t)bj * DD + d] = fmaf(wi, qv, wc);

    float v = qv * wq;
    #pragma unroll
    for (int o = 16; o > 0; o >>= 1) v += __shfl_xor_sync(0xffffffffu, v, o);
    __shared__ float red[8];
    if ((threadIdx.x & 31) == 0) red[threadIdx.x >> 5] = v;
    __syncthreads();
    if (threadIdx.x == 0) {
        float s = 0.f;
        #pragma unroll
        for (int i = 0; i < 8; i++) s += red[i];
        g_t[bj] = s + bias[0];
    }
}

// ---------------------------------------------------------------------------
// K1: S = contex @ Q'^T + t via tf32 mma, fused row softmax.
// Block tile 128(i) x 64(j), 256 thr = 8 warps (each 16x64), K=256.
// Register-staged double-buffered smem pipeline. grid=(4, B)
// ---------------------------------------------------------------------------
__global__ void __launch_bounds__(256) k1_score(const float* __restrict__ contex) {
    const int b  = blockIdx.y;
    const int i0 = blockIdx.x * 128;
    const int tid = threadIdx.x;
    const int warp = tid >> 5, lane = tid & 31;
    const int g = lane >> 2, t = lane & 3;
    const int wm = warp * 16;

    extern __shared__ float sm[];
    float* As = sm;                         // 2 x 128 x 36
    float* Bs = sm + 2 * 128 * 36;          // 2 x 64 x 36
    float* ts = Bs + 2 * 64 * 36;           // 64
    if (tid < 64) ts[tid] = g_t[b * LQQ + tid];

    const float* Cb = contex + (size_t)b * LCC * DD;
    const float* Qp = g_Qp  + (size_t)b * LQQ * DD;

    const int alr = tid >> 1, ako = (tid & 1) * 16;   // A fill: 4x float4
    const int bjr = tid >> 2, bko = (tid & 3) * 8;    // B fill: 2x float4

    float4 ra[4], rb[2];
    float acc[8][4];
    #pragma unroll
    for (int nt = 0; nt < 8; nt++)
        #pragma unroll
        for (int r = 0; r < 4; r++) acc[nt][r] = 0.f;

    // initial stage
    {
        const float* s = &Cb[(size_t)(i0 + alr) * DD + ako];
        ra[0] = *(const float4*)&s[0];  ra[1] = *(const float4*)&s[4];
        ra[2] = *(const float4*)&s[8];  ra[3] = *(const float4*)&s[12];
        const float* qs = &Qp[(size_t)bjr * DD + bko];
        rb[0] = *(const float4*)&qs[0]; rb[1] = *(const float4*)&qs[4];
        unsigned* da = (unsigned*)&As[(size_t)alr * 36 + ako];
        cvst4(da, ra[0]); cvst4(da + 4, ra[1]); cvst4(da + 8, ra[2]); cvst4(da + 12, ra[3]);
        unsigned* db = (unsigned*)&Bs[(size_t)bjr * 36 + bko];
        cvst4(db, rb[0]); cvst4(db + 4, rb[1]);
    }
    __syncthreads();

    #pragma unroll
    for (int it = 0; it < 8; it++) {
        const int buf = it & 1;
        if (it < 7) {
            const int kk = (it + 1) * 32;
            const float* s = &Cb[(size_t)(i0 + alr) * DD + kk + ako];
            ra[0] = *(const float4*)&s[0];  ra[1] = *(const float4*)&s[4];
            ra[2] = *(const float4*)&s[8];  ra[3] = *(const float4*)&s[12];
            const float* qs = &Qp[(size_t)bjr * DD + kk + bko];
            rb[0] = *(const float4*)&qs[0]; rb[1] = *(const float4*)&qs[4];
        }
        const float* Ab = As + (size_t)buf * 128 * 36;
        const float* Bb = Bs + (size_t)buf * 64 * 36;
        #pragma unroll
        for (int kc = 0; kc < 32; kc += 8) {
            unsigned a0 = *(const unsigned*)&Ab[(size_t)(wm + g) * 36 + kc + t];
            unsigned a1 = *(const unsigned*)&Ab[(size_t)(wm + 8 + g) * 36 + kc + t];
            unsigned a2 = *(const unsigned*)&Ab[(size_t)(wm + g) * 36 + kc + t + 4];
            unsigned a3 = *(const unsigned*)&Ab[(size_t)(wm + 8 + g) * 36 + kc + t + 4];
            #pragma unroll
            for (int nt = 0; nt < 8; nt++) {
                unsigned b0 = *(const unsigned*)&Bb[(size_t)(nt * 8 + g) * 36 + kc + t];
                unsigned b1 = *(const unsigned*)&Bb[(size_t)(nt * 8 + g) * 36 + kc + t + 4];
                mma8(acc[nt][0], acc[nt][1], acc[nt][2], acc[nt][3],
                     a0, a1, a2, a3, b0, b1);
            }
        }
        if (it < 7) {
            const int nb = (it + 1) & 1;
            unsigned* da = (unsigned*)&As[((size_t)nb * 128 + alr) * 36 + ako];
            cvst4(da, ra[0]); cvst4(da + 4, ra[1]); cvst4(da + 8, ra[2]); cvst4(da + 12, ra[3]);
            unsigned* db = (unsigned*)&Bs[((size_t)nb * 64 + bjr) * 36 + bko];
            cvst4(db, rb[0]); cvst4(db + 4, rb[1]);
        }
        __syncthreads();
    }

    // epilogue: +t[j], raw S^T out, row softmax -> S1
    float* Stb = g_St + (size_t)b * LQQ * LCC;
    float* S1b = g_S1 + (size_t)b * LCC * LQQ;
    #pragma unroll
    for (int h = 0; h < 2; h++) {
        const int i = i0 + wm + h * 8 + g;
        float s[16];
        #pragma unroll
        for (int nt = 0; nt < 8; nt++) {
            s[2 * nt]     = acc[nt][2 * h]     + ts[nt * 8 + 2 * t];
            s[2 * nt + 1] = acc[nt][2 * h + 1] + ts[nt * 8 + 2 * t + 1];
        }
        #pragma unroll
        for (int nt = 0; nt < 8; nt++) {
            Stb[(size_t)(nt * 8 + 2 * t) * LCC + i]     = s[2 * nt];
            Stb[(size_t)(nt * 8 + 2 * t + 1) * LCC + i] = s[2 * nt + 1];
        }
        float m = s[0];
        #pragma unroll
        for (int c = 1; c < 16; c++) m = fmaxf(m, s[c]);
        m = fmaxf(m, __shfl_xor_sync(0xffffffffu, m, 1));
        m = fmaxf(m, __shfl_xor_sync(0xffffffffu, m, 2));
        float e[16], sum = 0.f;
        #pragma unroll
        for (int c = 0; c < 16; c++) { e[c] = expf(s[c] - m); sum += e[c]; }
        sum += __shfl_xor_sync(0xffffffffu, sum, 1);
        sum += __shfl_xor_sync(0xffffffffu, sum, 2);
        const float inv = 1.f / sum;
        #pragma unroll
        for (int nt = 0; nt < 8; nt++) {
            float2 o = make_float2(e[2 * nt] * inv, e[2 * nt + 1] * inv);
            *(float2*)&S1b[(size_t)i * LQQ + nt * 8 + 2 * t] = o;
        }
    }
}

// ---------------------------------------------------------------------------
// K2: column softmax (length 512) in place on g_St rows.
// ---------------------------------------------------------------------------
__global__ void k2_colsm() {
    const int bj = blockIdx.x;
    float* row = g_St + (size_t)bj * LCC;
    const int tid = threadIdx.x;
    float v0 = row[tid], v1 = row[tid + 256];

    __shared__ float red[8];
    float m = fmaxf(v0, v1);
    #pragma unroll
    for (int o = 16; o > 0; o >>= 1) m = fmaxf(m, __shfl_xor_sync(0xffffffffu, m, o));
    if ((tid & 31) == 0) red[tid >> 5] = m;
    __syncthreads();
    m = fmaxf(fmaxf(fmaxf(red[0], red[1]), fmaxf(red[2], red[3])),
              fmaxf(fmaxf(red[4], red[5]), fmaxf(red[6], red[7])));
    __syncthreads();

    float e0 = expf(v0 - m), e1 = expf(v1 - m);
    float s = e0 + e1;
    #pragma unroll
    for (int o = 16; o > 0; o >>= 1) s += __shfl_xor_sync(0xffffffffu, s, o);
    if ((tid & 31) == 0) red[tid >> 5] = s;
    __syncthreads();
    s = red[0] + red[1] + red[2] + red[3] + red[4] + red[5] + red[6] + red[7];
    const float inv = 1.f / s;
    row[tid]       = e0 * inv;
    row[tid + 256] = e1 * inv;
}

// ---------------------------------------------------------------------------
// K3: C2 = S2^T @ contex via tf32 mma. Block tile 64(j) x 128(d), K split 2.
// 256 thr = 8 warps in 2(m) x 4(n), warp tile 32x32. Reg-staged double buffer.
// grid=(2, B, 2)
// ---------------------------------------------------------------------------
__global__ void __launch_bounds__(256) k3_c2(const float* __restrict__ contex) {
    const int b   = blockIdx.y;
    const int n0  = blockIdx.x * 128;
    const int kk0 = blockIdx.z * 256;
    const int tid = threadIdx.x;
    const int warp = tid >> 5, lane = tid & 31;
    const int g = lane >> 2, t = lane & 3;
    const int wm = (warp & 1) * 32;
    const int wn = (warp >> 1) * 32;

    extern __shared__ float sm3[];
    float* As = sm3;                        // 2 x 64 x 36  [j][k]
    float* Bs = sm3 + 2 * 64 * 36;          // 2 x 32 x 136 [k][n]

    const float* S2t = g_St + (size_t)b * LQQ * LCC;
    const float* Cb  = contex + (size_t)b * LCC * DD;

    const int ajr = tid >> 2, ako = (tid & 3) * 8;    // A fill: 2x float4
    const int bkr = tid >> 3, bnc = (tid & 7) * 16;   // B fill: 4x float4

    float4 ra[2], rb[4];
    float acc[2][4][4];
    #pragma unroll
    for (int mt = 0; mt < 2; mt++)
        #pragma unroll
        for (int nt = 0; nt < 4; nt++)
            #pragma unroll
            for (int r = 0; r < 4; r++) acc[mt][nt][r] = 0.f;

    {
        const float* s = &S2t[(size_t)ajr * LCC + kk0 + ako];
        ra[0] = *(const float4*)&s[0]; ra[1] = *(const float4*)&s[4];
        const float* c = &Cb[(size_t)(kk0 + bkr) * DD + n0 + bnc];
        rb[0] = *(const float4*)&c[0];  rb[1] = *(const float4*)&c[4];
        rb[2] = *(const float4*)&c[8];  rb[3] = *(const float4*)&c[12];
        unsigned* da = (unsigned*)&As[(size_t)ajr * 36 + ako];
        cvst4(da, ra[0]); cvst4(da + 4, ra[1]);
        unsigned* db = (unsigned*)&Bs[(size_t)bkr * 136 + bnc];
        cvst4(db, rb[0]); cvst4(db + 4, rb[1]); cvst4(db + 8, rb[2]); cvst4(db + 12, rb[3]);
    }
    __syncthreads();

    #pragma unroll
    for (int it = 0; it < 8; it++) {
        const int buf = it & 1;
        if (it < 7) {
            const int kk = kk0 + (it + 1) * 32;
            const float* s = &S2t[(size_t)ajr * LCC + kk + ako];
            ra[0] = *(const float4*)&s[0]; ra[1] = *(const float4*)&s[4];
            const float* c = &Cb[(size_t)(kk + bkr) * DD + n0 + bnc];
            rb[0] = *(const float4*)&c[0];  rb[1] = *(const float4*)&c[4];
            rb[2] = *(const float4*)&c[8];  rb[3] = *(const float4*)&c[12];
        }
        const float* Ab = As + (size_t)buf * 64 * 36;
        const float* Bb = Bs + (size_t)buf * 32 * 136;
        #pragma unroll
        for (int kc = 0; kc < 32; kc += 8) {
            unsigned a[2][4];
            #pragma unroll
            for (int mt = 0; mt < 2; mt++) {
                const int r = wm + mt * 16 + g;
                a[mt][0] = *(const unsigned*)&Ab[(size_t)r * 36 + kc + t];
                a[mt][1] = *(const unsigned*)&Ab[(size_t)(r + 8) * 36 + kc + t];
                a[mt][2] = *(const unsigned*)&Ab[(size_t)r * 36 + kc + t + 4];
                a[mt][3] = *(const unsigned*)&Ab[(size_t)(r + 8) * 36 + kc + t + 4];
            }
            #pragma unroll
            for (int nt = 0; nt < 4; nt++) {
                const int n = wn + nt * 8 + g;
                unsigned b0 = *(const unsigned*)&Bb[(size_t)(kc + t) * 136 + n];
                unsigned b1 = *(const unsigned*)&Bb[(size_t)(kc + t + 4) * 136 + n];
                mma8(acc[0][nt][0], acc[0][nt][1], acc[0][nt][2], acc[0][nt][3],
                     a[0][0], a[0][1], a[0][2], a[0][3], b0, b1);
                mma8(acc[1][nt][0], acc[1][nt][1], acc[1][nt][2], acc[1][nt][3],
                     a[1][0], a[1][1], a[1][2], a[1][3], b0, b1);
            }
        }
        if (it < 7) {
            const int nb = (it + 1) & 1;
            unsigned* da = (unsigned*)&As[((size_t)nb * 64 + ajr) * 36 + ako];
            cvst4(da, ra[0]); cvst4(da + 4, ra[1]);
            unsigned* db = (unsigned*)&Bs[((size_t)nb * 32 + bkr) * 136 + bnc];
            cvst4(db, rb[0]); cvst4(db + 4, rb[1]); cvst4(db + 8, rb[2]); cvst4(db + 12, rb[3]);
        }
        __syncthreads();
    }

    float* outp = g_C2p + (size_t)blockIdx.z * BB * LQQ * DD + (size_t)b * LQQ * DD;
    #pragma unroll
    for (int mt = 0; mt < 2; mt++)
        #pragma unroll
        for (int h = 0; h < 2; h++) {
            const int j = wm + mt * 16 + h * 8 + g;
            #pragma unroll
            for (int nt = 0; nt < 4; nt++) {
                float2 o = make_float2(acc[mt][nt][2 * h], acc[mt][nt][2 * h + 1]);
                *(float2*)&outp[(size_t)j * DD + n0 + wn + nt * 8 + 2 * t] = o;
            }
        }
}

// ---------------------------------------------------------------------------
// K4: A = S1 @ question, Bm = S1 @ (C2p0+C2p1) via tf32 mma (K=64),
// fused output assembly: out[b,i] = [contex | A | contex*A | contex*Bm]
// Block tile 128(i) x 64 per chunk, 8 chunks. 256 thr = 8 warps (16x64 each).
// B-chunk double buffered with reg staging. grid=(4, B).
// ---------------------------------------------------------------------------
__global__ void __launch_bounds__(256) k4_out(const float* __restrict__ contex,
                                              const float* __restrict__ question,
                                              float* __restrict__ out) {
    const int b  = blockIdx.y;
    const int i0 = blockIdx.x * 128;
    const int tid = threadIdx.x;
    const int warp = tid >> 5, lane = tid & 31;
    const int g = lane >> 2, t = lane & 3;
    const int wm = warp * 16;

    extern __shared__ float sm4[];
    float* As = sm4;                        // 128 x 68  [i][j]  (persistent)
    float* Bs = sm4 + 128 * 68;             // 2 x 64 x 72 [j][n]

    const float* S1b = g_S1 + (size_t)b * LCC * LQQ;
    {   // fill A once (tf32)
        const int lr = tid >> 1, jo = (tid & 1) * 32;
        const float* src = &S1b[(size_t)(i0 + lr) * LQQ + jo];
        unsigned* dst = (unsigned*)&As[(size_t)lr * 68 + jo];
        #pragma unroll
        for (int u = 0; u < 8; u++) cvst4(dst + u * 4, *(const float4*)&src[u * 4]);
    }

    const float* Cb = contex   + (size_t)b * LCC * DD;
    const float* Qb = question + (size_t)b * LQQ * DD;
    const float* P0 = g_C2p    + (size_t)b * LQQ * DD;
    const float* P1 = g_C2p + (size_t)BB * LQQ * DD + (size_t)b * LQQ * DD;
    float* outb = out + (size_t)b * LCC * 1024;

    const int bjr = tid >> 2, boff = (tid & 3) * 16;   // B fill: 4x float4
    float4 rb[4];

    auto ldB = [&](int chunk) {
        const int c0 = (chunk & 3) * 64;
        if (chunk < 4) {
            const float* src = &Qb[(size_t)bjr * DD + c0 + boff];
            rb[0] = *(const float4*)&src[0];  rb[1] = *(const float4*)&src[4];
            rb[2] = *(const float4*)&src[8];  rb[3] = *(const float4*)&src[12];
        } else {
            const float* s0 = &P0[(size_t)bjr * DD + c0 + boff];
            const float* s1 = &P1[(size_t)bjr * DD + c0 + boff];
            #pragma unroll
            for (int u = 0; u < 4; u++) {
                float4 x = *(const float4*)&s0[u * 4];
                float4 y = *(const float4*)&s1[u * 4];
                rb[u] = make_float4(x.x + y.x, x.y + y.y, x.z + y.z, x.w + y.w);
            }
        }
    };
    auto stB = [&](int buf) {
        unsigned* dst = (unsigned*)&Bs[((size_t)buf * 64 + bjr) * 72 + boff];
        cvst4(dst, rb[0]); cvst4(dst + 4, rb[1]); cvst4(dst + 8, rb[2]); cvst4(dst + 12, rb[3]);
    };

    ldB(0); stB(0);
    __syncthreads();

    for (int chunk = 0; chunk < 8; chunk++) {
        const int buf = chunk & 1;
        const int c0 = (chunk & 3) * 64;
        if (chunk < 7) ldB(chunk + 1);

        float acc[8][4];
        #pragma unroll
        for (int nt = 0; nt < 8; nt++)
            #pragma unroll
            for (int r = 0; r < 4; r++) acc[nt][r] = 0.f;

        const float* Bb = Bs + (size_t)buf * 64 * 72;
        #pragma unroll
        for (int kc = 0; kc < 64; kc += 8) {
            unsigned a0 = *(const unsigned*)&As[(size_t)(wm + g) * 68 + kc + t];
            unsigned a1 = *(const unsigned*)&As[(size_t)(wm + 8 + g) * 68 + kc + t];
            unsigned a2 = *(const unsigned*)&As[(size_t)(wm + g) * 68 + kc + t + 4];
            unsigned a3 = *(const unsigned*)&As[(size_t)(wm + 8 + g) * 68 + kc + t + 4];
            #pragma unroll
            for (int nt = 0; nt < 8; nt++) {
                const int n = nt * 8 + g;
                unsigned b0 = *(const unsigned*)&Bb[(size_t)(kc + t) * 72 + n];
                unsigned b1 = *(const unsigned*)&Bb[(size_t)(kc + t + 4) * 72 + n];
                mma8(acc[nt][0], acc[nt][1], acc[nt][2], acc[nt][3],
                     a0, a1, a2, a3, b0, b1);
            }
        }

        // epilogue: assemble output (contex from gmem, L2-resident)
        #pragma unroll
        for (int h = 0; h < 2; h++) {
            const int i = i0 + wm + h * 8 + g;
            const float* crow = &Cb[(size_t)i * DD];
            float* orow = &outb[(size_t)i * 1024];
            #pragma unroll
            for (int nt = 0; nt < 8; nt++) {
                const int col = c0 + nt * 8 + 2 * t;
                float2 cv = *(const float2*)&crow[col];
                float2 av = make_float2(acc[nt][2 * h], acc[nt][2 * h + 1]);
                float2 pv = make_float2(cv.x * av.x, cv.y * av.y);
                if (chunk < 4) {
                    *(float2*)&orow[col]       = cv;   // contex
                    *(float2*)&orow[256 + col] = av;   // A
                    *(float2*)&orow[512 + col] = pv;   // contex * A
                } else {
                    *(float2*)&orow[768 + col] = pv;   // contex * Bm
                }
            }
        }

        if (chunk < 7) stB(buf ^ 1);
        __syncthreads();
    }
}

// ---------------------------------------------------------------------------
extern "C" void kernel_launch(void* const* d_in, const int* in_sizes, int n_in,
                              void* d_out, int out_size) {
    const float* contex   = (const float*)d_in[0];
    const float* question = (const float*)d_in[1];
    const float* W        = (const float*)d_in[2];
    const float* bias     = (const float*)d_in[3];
    float* out = (float*)d_out;

    const int k1smem = (2 * 128 * 36 + 2 * 64 * 36 + 64) * (int)sizeof(float);  // 55552
    const int k3smem = (2 * 64 * 36 + 2 * 32 * 136) * (int)sizeof(float);       // 53248
    const int k4smem = (128 * 68 + 2 * 64 * 72) * (int)sizeof(float);           // 71680
    cudaFuncSetAttribute(k1_score, cudaFuncAttributeMaxDynamicSharedMemorySize, k1smem);
    cudaFuncSetAttribute(k3_c2,    cudaFuncAttributeMaxDynamicSharedMemorySize, k3smem);
    cudaFuncSetAttribute(k4_out,   cudaFuncAttributeMaxDynamicSharedMemorySize, k4smem);

    k0_prep<<<BB * LQQ, 256>>>(question, W, bias);
    k1_score<<<dim3(4, BB), 256, k1smem>>>(contex);
    k2_colsm<<<BB * LQQ, 256>>>();
    k3_c2<<<dim3(2, BB, 2), 256, k3smem>>>(contex);
    k4_out<<<dim3(4, BB), 256, k4smem>>>(contex, question, out);
}

// round 6
// speedup vs baseline: 2.6105x; 1.1152x over previous
#include <cuda_runtime.h>
#include <math.h>

#define BB  64
#define LCC 512
#define LQQ 64
#define DD  256

// ---------------------------------------------------------------------------
// tf32 mma helpers (m16n8k8, row.col, fp32 accum)
// ---------------------------------------------------------------------------
__device__ __forceinline__ unsigned tf32c(float x) {
    unsigned r; asm("cvt.rna.tf32.f32 %0, %1;" : "=r"(r) : "f"(x)); return r;
}
__device__ __forceinline__ void mma8(float& d0, float& d1, float& d2, float& d3,
                                     unsigned a0, unsigned a1, unsigned a2, unsigned a3,
                                     unsigned b0, unsigned b1) {
    asm("mma.sync.aligned.m16n8k8.row.col.f32.tf32.tf32.f32 "
        "{%0,%1,%2,%3},{%4,%5,%6,%7},{%8,%9},{%0,%1,%2,%3};"
        : "+f"(d0), "+f"(d1), "+f"(d2), "+f"(d3)
        : "r"(a0), "r"(a1), "r"(a2), "r"(a3), "r"(b0), "r"(b1));
}
__device__ __forceinline__ void cvst4(unsigned* dst, float4 v) {
    dst[0] = tf32c(v.x); dst[1] = tf32c(v.y); dst[2] = tf32c(v.z); dst[3] = tf32c(v.w);
}

// Scratch (device globals; no allocation allowed)
__device__ float g_t[BB * LQQ];                          // <q,wq> + bias
__device__ float g_S1[(size_t)BB * LCC * LQQ];           // row-softmax(S)
__device__ float g_St[(size_t)BB * LQQ * LCC];           // raw S^T (logits)
__device__ float g_cpart[4 * BB * LQQ];                  // per-i-block col expsum partials
__device__ float g_inv[BB * LQQ];                        // 1 / col expsum
__device__ float g_C2p[2 * (size_t)BB * LQQ * DD];       // S2^T @ contex (2 K-split partials)

// ---------------------------------------------------------------------------
// K0: t[b,j] = <q[b,j], wq> + bias
// ---------------------------------------------------------------------------
__global__ void k0_t(const float* __restrict__ q,
                     const float* __restrict__ W,
                     const float* __restrict__ bias) {
    const int bj = blockIdx.x;
    const int d  = threadIdx.x;
    float v = q[(size_t)bj * DD + d] * W[d];
    #pragma unroll
    for (int o = 16; o > 0; o >>= 1) v += __shfl_xor_sync(0xffffffffu, v, o);
    __shared__ float red[8];
    if ((threadIdx.x & 31) == 0) red[threadIdx.x >> 5] = v;
    __syncthreads();
    if (threadIdx.x == 0) {
        float s = 0.f;
        #pragma unroll
        for (int i = 0; i < 8; i++) s += red[i];
        g_t[bj] = s + bias[0];
    }
}

// ---------------------------------------------------------------------------
// K1: S = contex @ Q'^T + t via tf32 mma (Q' = wi*q+wc built in-fill).
// Block 128(i) x 64(j), 256 thr = 8 warps (16x64), K=256, reg-staged dbuf.
// Outputs: S1 (row softmax), raw S^T (coalesced), per-block col expsum partials.
// grid=(4, B)
// ---------------------------------------------------------------------------
__global__ void __launch_bounds__(256, 2) k1_score(const float* __restrict__ contex,
                                                   const float* __restrict__ question,
                                                   const float* __restrict__ W) {
    const int b  = blockIdx.y;
    const int i0 = blockIdx.x * 128;
    const int tid = threadIdx.x;
    const int warp = tid >> 5, lane = tid & 31;
    const int g = lane >> 2, t = lane & 3;
    const int wm = warp * 16;

    extern __shared__ float sm[];
    float* As   = sm;                 // 2 x 128 x 36 = 9216
    float* Bs   = sm + 9216;          // 2 x 64 x 36  = 4608
    float* ts   = sm + 13824;         // 64
    float* scol = sm + 13888;         // 8 x 64 = 512
    if (tid < 64) ts[tid] = g_t[b * LQQ + tid];

    const float* Cb = contex   + (size_t)b * LCC * DD;
    const float* Qb = question + (size_t)b * LQQ * DD;

    const int alr = tid >> 1, ako = (tid & 1) * 16;   // A fill: 4x float4
    const int bjr = tid >> 2, bko = (tid & 3) * 8;    // B fill: 2x float4

    float4 ra[4], rb[2];
    float acc[8][4];
    #pragma unroll
    for (int nt = 0; nt < 8; nt++)
        #pragma unroll
        for (int r = 0; r < 4; r++) acc[nt][r] = 0.f;

    auto ldStage = [&](int kk) {
        const float* s = &Cb[(size_t)(i0 + alr) * DD + kk + ako];
        ra[0] = *(const float4*)&s[0];  ra[1] = *(const float4*)&s[4];
        ra[2] = *(const float4*)&s[8];  ra[3] = *(const float4*)&s[12];
        const float* qs = &Qb[(size_t)bjr * DD + kk + bko];
        rb[0] = *(const float4*)&qs[0]; rb[1] = *(const float4*)&qs[4];
    };
    auto stStage = [&](int buf, int kk) {
        unsigned* da = (unsigned*)&As[((size_t)buf * 128 + alr) * 36 + ako];
        cvst4(da, ra[0]); cvst4(da + 4, ra[1]); cvst4(da + 8, ra[2]); cvst4(da + 12, ra[3]);
        // Q' = wi*q + wc on the fly
        float4 wi0 = *(const float4*)&W[512 + kk + bko];
        float4 wi1 = *(const float4*)&W[512 + kk + bko + 4];
        float4 wc0 = *(const float4*)&W[256 + kk + bko];
        float4 wc1 = *(const float4*)&W[256 + kk + bko + 4];
        float4 q0 = make_float4(fmaf(wi0.x, rb[0].x, wc0.x), fmaf(wi0.y, rb[0].y, wc0.y),
                                fmaf(wi0.z, rb[0].z, wc0.z), fmaf(wi0.w, rb[0].w, wc0.w));
        float4 q1 = make_float4(fmaf(wi1.x, rb[1].x, wc1.x), fmaf(wi1.y, rb[1].y, wc1.y),
                                fmaf(wi1.z, rb[1].z, wc1.z), fmaf(wi1.w, rb[1].w, wc1.w));
        unsigned* db = (unsigned*)&Bs[((size_t)buf * 64 + bjr) * 36 + bko];
        cvst4(db, q0); cvst4(db + 4, q1);
    };

    ldStage(0); stStage(0, 0);
    __syncthreads();

    #pragma unroll
    for (int it = 0; it < 8; it++) {
        const int buf = it & 1;
        if (it < 7) ldStage((it + 1) * 32);
        const float* Ab = As + (size_t)buf * 128 * 36;
        const float* Bb = Bs + (size_t)buf * 64 * 36;
        #pragma unroll
        for (int kc = 0; kc < 32; kc += 8) {
            unsigned a0 = *(const unsigned*)&Ab[(size_t)(wm + g) * 36 + kc + t];
            unsigned a1 = *(const unsigned*)&Ab[(size_t)(wm + 8 + g) * 36 + kc + t];
            unsigned a2 = *(const unsigned*)&Ab[(size_t)(wm + g) * 36 + kc + t + 4];
            unsigned a3 = *(const unsigned*)&Ab[(size_t)(wm + 8 + g) * 36 + kc + t + 4];
            #pragma unroll
            for (int nt = 0; nt < 8; nt++) {
                unsigned b0 = *(const unsigned*)&Bb[(size_t)(nt * 8 + g) * 36 + kc + t];
                unsigned b1 = *(const unsigned*)&Bb[(size_t)(nt * 8 + g) * 36 + kc + t + 4];
                mma8(acc[nt][0], acc[nt][1], acc[nt][2], acc[nt][3],
                     a0, a1, a2, a3, b0, b1);
            }
        }
        if (it < 7) stStage(buf ^ 1, (it + 1) * 32);
        __syncthreads();
    }

    // ---- epilogue ----
    float* Ssm = sm;                         // reuse As region: 64 x 132 (33792 <= 9216*4B? yes floats)
    float* S1b = g_S1 + (size_t)b * LCC * LQQ;
    float cs[16];
    #pragma unroll
    for (int c = 0; c < 16; c++) cs[c] = 0.f;

    #pragma unroll
    for (int h = 0; h < 2; h++) {
        const int il = wm + h * 8 + g;       // local i in [0,128)
        const int i  = i0 + il;
        float s[16];
        #pragma unroll
        for (int nt = 0; nt < 8; nt++) {
            s[2 * nt]     = acc[nt][2 * h]     + ts[nt * 8 + 2 * t];
            s[2 * nt + 1] = acc[nt][2 * h + 1] + ts[nt * 8 + 2 * t + 1];
        }
        // stage raw S^T into smem [j][i_local]
        #pragma unroll
        for (int c = 0; c < 16; c++) {
            const int j = (c >> 1) * 8 + 2 * t + (c & 1);
            Ssm[(size_t)j * 132 + il] = s[c];
        }
        // column expsum partials (no max; |S| << 88)
        #pragma unroll
        for (int c = 0; c < 16; c++) cs[c] += expf(s[c]);
        // row softmax -> S1
        float m = s[0];
        #pragma unroll
        for (int c = 1; c < 16; c++) m = fmaxf(m, s[c]);
        m = fmaxf(m, __shfl_xor_sync(0xffffffffu, m, 1));
        m = fmaxf(m, __shfl_xor_sync(0xffffffffu, m, 2));
        float e[16], sum = 0.f;
        #pragma unroll
        for (int c = 0; c < 16; c++) { e[c] = expf(s[c] - m); sum += e[c]; }
        sum += __shfl_xor_sync(0xffffffffu, sum, 1);
        sum += __shfl_xor_sync(0xffffffffu, sum, 2);
        const float inv = 1.f / sum;
        #pragma unroll
        for (int nt = 0; nt < 8; nt++) {
            float2 o = make_float2(e[2 * nt] * inv, e[2 * nt + 1] * inv);
            *(float2*)&S1b[(size_t)i * LQQ + nt * 8 + 2 * t] = o;
        }
    }
    // reduce col partials over g (8 i-slots x 2h = warp's 16 rows)
    #pragma unroll
    for (int c = 0; c < 16; c++) {
        cs[c] += __shfl_xor_sync(0xffffffffu, cs[c], 4);
        cs[c] += __shfl_xor_sync(0xffffffffu, cs[c], 8);
        cs[c] += __shfl_xor_sync(0xffffffffu, cs[c], 16);
    }
    if (g == 0) {
        #pragma unroll
        for (int c = 0; c < 16; c++) {
            const int j = (c >> 1) * 8 + 2 * t + (c & 1);
            scol[warp * 64 + j] = cs[c];
        }
    }
    __syncthreads();

    // coalesced raw S^T write: 64 rows x 128 cols
    {
        const int r = tid >> 2, co = (tid & 3) * 32;
        float* dst = &g_St[((size_t)b * LQQ + r) * LCC + i0 + co];
        const float* src = &Ssm[(size_t)r * 132 + co];
        #pragma unroll
        for (int u = 0; u < 8; u++)
            *(float4*)&dst[u * 4] = *(const float4*)&src[u * 4];
    }
    if (tid < 64) {
        float p = 0.f;
        #pragma unroll
        for (int w = 0; w < 8; w++) p += scol[w * 64 + tid];
        g_cpart[blockIdx.x * (BB * LQQ) + b * LQQ + tid] = p;
    }
}

// ---------------------------------------------------------------------------
// K2c: combine 4 per-block col expsum partials -> inv. grid=(B), 64 thr.
// ---------------------------------------------------------------------------
__global__ void k2c_inv() {
    const int idx = blockIdx.x * LQQ + threadIdx.x;
    float s = g_cpart[idx] + g_cpart[BB * LQQ + idx]
            + g_cpart[2 * BB * LQQ + idx] + g_cpart[3 * BB * LQQ + idx];
    g_inv[idx] = 1.f / s;
}

// ---------------------------------------------------------------------------
// K3: C2 = S2^T @ contex via tf32 mma; S2 = exp(rawSt)*inv applied in-fill.
// Block 64(j) x 128(d), K split 2; 256 thr = 8 warps 2(m)x4(n), 32x32 tiles.
// grid=(2, B, 2)
// ---------------------------------------------------------------------------
__global__ void __launch_bounds__(256, 2) k3_c2(const float* __restrict__ contex) {
    const int b   = blockIdx.y;
    const int n0  = blockIdx.x * 128;
    const int kk0 = blockIdx.z * 256;
    const int tid = threadIdx.x;
    const int warp = tid >> 5, lane = tid & 31;
    const int g = lane >> 2, t = lane & 3;
    const int wm = (warp & 1) * 32;
    const int wn = (warp >> 1) * 32;

    extern __shared__ float sm3[];
    float* As = sm3;                        // 2 x 64 x 36  [j][k]
    float* Bs = sm3 + 2 * 64 * 36;          // 2 x 32 x 136 [k][n]

    const float* S2t = g_St + (size_t)b * LQQ * LCC;
    const float* Cb  = contex + (size_t)b * LCC * DD;

    const int ajr = tid >> 2, ako = (tid & 3) * 8;    // A fill: 2x float4
    const int bkr = tid >> 3, bnc = (tid & 7) * 16;   // B fill: 4x float4
    const float invj = g_inv[b * LQQ + ajr];

    float4 ra[2], rb[4];
    float acc[2][4][4];
    #pragma unroll
    for (int mt = 0; mt < 2; mt++)
        #pragma unroll
        for (int nt = 0; nt < 4; nt++)
            #pragma unroll
            for (int r = 0; r < 4; r++) acc[mt][nt][r] = 0.f;

    auto ldStage = [&](int kk) {
        const float* s = &S2t[(size_t)ajr * LCC + kk + ako];
        ra[0] = *(const float4*)&s[0]; ra[1] = *(const float4*)&s[4];
        const float* c = &Cb[(size_t)(kk + bkr) * DD + n0 + bnc];
        rb[0] = *(const float4*)&c[0];  rb[1] = *(const float4*)&c[4];
        rb[2] = *(const float4*)&c[8];  rb[3] = *(const float4*)&c[12];
    };
    auto stStage = [&](int buf) {
        unsigned* da = (unsigned*)&As[((size_t)buf * 64 + ajr) * 36 + ako];
        float4 e0 = make_float4(expf(ra[0].x) * invj, expf(ra[0].y) * invj,
                                expf(ra[0].z) * invj, expf(ra[0].w) * invj);
        float4 e1 = make_float4(expf(ra[1].x) * invj, expf(ra[1].y) * invj,
                                expf(ra[1].z) * invj, expf(ra[1].w) * invj);
        cvst4(da, e0); cvst4(da + 4, e1);
        unsigned* db = (unsigned*)&Bs[((size_t)buf * 32 + bkr) * 136 + bnc];
        cvst4(db, rb[0]); cvst4(db + 4, rb[1]); cvst4(db + 8, rb[2]); cvst4(db + 12, rb[3]);
    };

    ldStage(kk0); stStage(0);
    __syncthreads();

    #pragma unroll
    for (int it = 0; it < 8; it++) {
        const int buf = it & 1;
        if (it < 7) ldStage(kk0 + (it + 1) * 32);
        const float* Ab = As + (size_t)buf * 64 * 36;
        const float* Bb = Bs + (size_t)buf * 32 * 136;
        #pragma unroll
        for (int kc = 0; kc < 32; kc += 8) {
            unsigned a[2][4];
            #pragma unroll
            for (int mt = 0; mt < 2; mt++) {
                const int r = wm + mt * 16 + g;
                a[mt][0] = *(const unsigned*)&Ab[(size_t)r * 36 + kc + t];
                a[mt][1] = *(const unsigned*)&Ab[(size_t)(r + 8) * 36 + kc + t];
                a[mt][2] = *(const unsigned*)&Ab[(size_t)r * 36 + kc + t + 4];
                a[mt][3] = *(const unsigned*)&Ab[(size_t)(r + 8) * 36 + kc + t + 4];
            }
            #pragma unroll
            for (int nt = 0; nt < 4; nt++) {
                const int n = wn + nt * 8 + g;
                unsigned b0 = *(const unsigned*)&Bb[(size_t)(kc + t) * 136 + n];
                unsigned b1 = *(const unsigned*)&Bb[(size_t)(kc + t + 4) * 136 + n];
                mma8(acc[0][nt][0], acc[0][nt][1], acc[0][nt][2], acc[0][nt][3],
                     a[0][0], a[0][1], a[0][2], a[0][3], b0, b1);
                mma8(acc[1][nt][0], acc[1][nt][1], acc[1][nt][2], acc[1][nt][3],
                     a[1][0], a[1][1], a[1][2], a[1][3], b0, b1);
            }
        }
        if (it < 7) stStage(buf ^ 1);
        __syncthreads();
    }

    float* outp = g_C2p + (size_t)blockIdx.z * BB * LQQ * DD + (size_t)b * LQQ * DD;
    #pragma unroll
    for (int mt = 0; mt < 2; mt++)
        #pragma unroll
        for (int h = 0; h < 2; h++) {
            const int j = wm + mt * 16 + h * 8 + g;
            #pragma unroll
            for (int nt = 0; nt < 4; nt++) {
                float2 o = make_float2(acc[mt][nt][2 * h], acc[mt][nt][2 * h + 1]);
                *(float2*)&outp[(size_t)j * DD + n0 + wn + nt * 8 + 2 * t] = o;
            }
        }
}

// ---------------------------------------------------------------------------
// K4: A = S1 @ question, Bm = S1 @ (C2p0+C2p1), dual-B per chunk (4 chunks),
// fused output: out[b,i] = [contex | A | contex*A | contex*Bm]
// Block 128(i), 256 thr = 8 warps (16x64). Double-buffered dual B tiles.
// grid=(4, B)
// ---------------------------------------------------------------------------
__global__ void __launch_bounds__(256) k4_out(const float* __restrict__ contex,
                                              const float* __restrict__ question,
                                              float* __restrict__ out) {
    const int b  = blockIdx.y;
    const int i0 = blockIdx.x * 128;
    const int tid = threadIdx.x;
    const int warp = tid >> 5, lane = tid & 31;
    const int g = lane >> 2, t = lane & 3;
    const int wm = warp * 16;

    extern __shared__ float sm4[];
    float* As = sm4;                        // 128 x 68 [i][j] persistent
    float* Bt = sm4 + 128 * 68;             // 2 buf x 2 tiles x 64 x 72

    const float* S1b = g_S1 + (size_t)b * LCC * LQQ;
    {   // fill A once (tf32)
        const int lr = tid >> 1, jo = (tid & 1) * 32;
        const float* src = &S1b[(size_t)(i0 + lr) * LQQ + jo];
        unsigned* dst = (unsigned*)&As[(size_t)lr * 68 + jo];
        #pragma unroll
        for (int u = 0; u < 8; u++) cvst4(dst + u * 4, *(const float4*)&src[u * 4]);
    }

    const float* Cb = contex   + (size_t)b * LCC * DD;
    const float* Qb = question + (size_t)b * LQQ * DD;
    const float* P0 = g_C2p    + (size_t)b * LQQ * DD;
    const float* P1 = g_C2p + (size_t)BB * LQQ * DD + (size_t)b * LQQ * DD;
    float* outb = out + (size_t)b * LCC * 1024;

    const int bjr = tid >> 2, boff = (tid & 3) * 16;   // per tile: 4x float4
    float4 rq[4], rc[4];

    auto ldB = [&](int chunk) {
        const int c0 = chunk * 64;
        const float* src = &Qb[(size_t)bjr * DD + c0 + boff];
        rq[0] = *(const float4*)&src[0];  rq[1] = *(const float4*)&src[4];
        rq[2] = *(const float4*)&src[8];  rq[3] = *(const float4*)&src[12];
        const float* s0 = &P0[(size_t)bjr * DD + c0 + boff];
        const float* s1 = &P1[(size_t)bjr * DD + c0 + boff];
        #pragma unroll
        for (int u = 0; u < 4; u++) {
            float4 x = *(const float4*)&s0[u * 4];
            float4 y = *(const float4*)&s1[u * 4];
            rc[u] = make_float4(x.x + y.x, x.y + y.y, x.z + y.z, x.w + y.w);
        }
    };
    auto stB = [&](int buf) {
        unsigned* dq = (unsigned*)&Bt[((size_t)buf * 128 + bjr) * 72 + boff];
        cvst4(dq, rq[0]); cvst4(dq + 4, rq[1]); cvst4(dq + 8, rq[2]); cvst4(dq + 12, rq[3]);
        unsigned* dc = (unsigned*)&Bt[((size_t)buf * 128 + 64 + bjr) * 72 + boff];
        cvst4(dc, rc[0]); cvst4(dc + 4, rc[1]); cvst4(dc + 8, rc[2]); cvst4(dc + 12, rc[3]);
    };

    ldB(0); stB(0);
    __syncthreads();

    #pragma unroll
    for (int chunk = 0; chunk < 4; chunk++) {
        const int buf = chunk & 1;
        const int c0 = chunk * 64;
        if (chunk < 3) ldB(chunk + 1);

        float accq[8][4], accc[8][4];
        #pragma unroll
        for (int nt = 0; nt < 8; nt++)
            #pragma unroll
            for (int r = 0; r < 4; r++) { accq[nt][r] = 0.f; accc[nt][r] = 0.f; }

        const float* Bq = Bt + (size_t)buf * 128 * 72;
        const float* Bc = Bq + 64 * 72;
        #pragma unroll
        for (int kc = 0; kc < 64; kc += 8) {
            unsigned a0 = *(const unsigned*)&As[(size_t)(wm + g) * 68 + kc + t];
            unsigned a1 = *(const unsigned*)&As[(size_t)(wm + 8 + g) * 68 + kc + t];
            unsigned a2 = *(const unsigned*)&As[(size_t)(wm + g) * 68 + kc + t + 4];
            unsigned a3 = *(const unsigned*)&As[(size_t)(wm + 8 + g) * 68 + kc + t + 4];
            #pragma unroll
            for (int nt = 0; nt < 8; nt++) {
                const int n = nt * 8 + g;
                unsigned q0 = *(const unsigned*)&Bq[(size_t)(kc + t) * 72 + n];
                unsigned q1 = *(const unsigned*)&Bq[(size_t)(kc + t + 4) * 72 + n];
                mma8(accq[nt][0], accq[nt][1], accq[nt][2], accq[nt][3],
                     a0, a1, a2, a3, q0, q1);
                unsigned c0r = *(const unsigned*)&Bc[(size_t)(kc + t) * 72 + n];
                unsigned c1r = *(const unsigned*)&Bc[(size_t)(kc + t + 4) * 72 + n];
                mma8(accc[nt][0], accc[nt][1], accc[nt][2], accc[nt][3],
                     a0, a1, a2, a3, c0r, c1r);
            }
        }

        // epilogue: contex read once; write all 4 output sections for cols c0..c0+63
        #pragma unroll
        for (int h = 0; h < 2; h++) {
            const int i = i0 + wm + h * 8 + g;
            const float* crow = &Cb[(size_t)i * DD];
            float* orow = &outb[(size_t)i * 1024];
            #pragma unroll
            for (int nt = 0; nt < 8; nt++) {
                const int col = c0 + nt * 8 + 2 * t;
                float2 cv = *(const float2*)&crow[col];
                float2 av = make_float2(accq[nt][2 * h], accq[nt][2 * h + 1]);
                float2 bv = make_float2(accc[nt][2 * h], accc[nt][2 * h + 1]);
                float2 pa = make_float2(cv.x * av.x, cv.y * av.y);
                float2 pb = make_float2(cv.x * bv.x, cv.y * bv.y);
                *(float2*)&orow[col]       = cv;   // contex
                *(float2*)&orow[256 + col] = av;   // A
                *(float2*)&orow[512 + col] = pa;   // contex * A
                *(float2*)&orow[768 + col] = pb;   // contex * Bm
            }
        }

        if (chunk < 3) stB(buf ^ 1);
        __syncthreads();
    }
}

// ---------------------------------------------------------------------------
extern "C" void kernel_launch(void* const* d_in, const int* in_sizes, int n_in,
                              void* d_out, int out_size) {
    const float* contex   = (const float*)d_in[0];
    const float* question = (const float*)d_in[1];
    const float* W        = (const float*)d_in[2];
    const float* bias     = (const float*)d_in[3];
    float* out = (float*)d_out;

    const int k1smem = 14400 * (int)sizeof(float);                          // 57600
    const int k3smem = (2 * 64 * 36 + 2 * 32 * 136) * (int)sizeof(float);   // 53248
    const int k4smem = (128 * 68 + 2 * 2 * 64 * 72) * (int)sizeof(float);   // 108544
    cudaFuncSetAttribute(k1_score, cudaFuncAttributeMaxDynamicSharedMemorySize, k1smem);
    cudaFuncSetAttribute(k3_c2,    cudaFuncAttributeMaxDynamicSharedMemorySize, k3smem);
    cudaFuncSetAttribute(k4_out,   cudaFuncAttributeMaxDynamicSharedMemorySize, k4smem);

    k0_t<<<BB * LQQ, 256>>>(question, W, bias);
    k1_score<<<dim3(4, BB), 256, k1smem>>>(contex, question, W);
    k2c_inv<<<BB, LQQ>>>();
    k3_c2<<<dim3(2, BB, 2), 256, k3smem>>>(contex);
    k4_out<<<dim3(4, BB), 256, k4smem>>>(contex, question, out);
}

// round 7
// speedup vs baseline: 2.6795x; 1.0264x over previous
#include <cuda_runtime.h>
#include <math.h>

#define BB  64
#define LCC 512
#define LQQ 64
#define DD  256

// ---------------------------------------------------------------------------
// tf32 mma (m16n8k8, row.col, fp32 accum) — operands are RAW fp32 bits
// (HW truncates mantissa to tf32; CUTLASS fast-path, no cvt needed)
// ---------------------------------------------------------------------------
__device__ __forceinline__ void mma8(float& d0, float& d1, float& d2, float& d3,
                                     unsigned a0, unsigned a1, unsigned a2, unsigned a3,
                                     unsigned b0, unsigned b1) {
    asm("mma.sync.aligned.m16n8k8.row.col.f32.tf32.tf32.f32 "
        "{%0,%1,%2,%3},{%4,%5,%6,%7},{%8,%9},{%0,%1,%2,%3};"
        : "+f"(d0), "+f"(d1), "+f"(d2), "+f"(d3)
        : "r"(a0), "r"(a1), "r"(a2), "r"(a3), "r"(b0), "r"(b1));
}
__device__ __forceinline__ unsigned sm2u(const void* p) {
    unsigned r;
    asm("{.reg .u64 t; cvta.to.shared.u64 t, %1; cvt.u32.u64 %0, t;}" : "=r"(r) : "l"(p));
    return r;
}
#define CPA16(dst, src) asm volatile("cp.async.ca.shared.global [%0], [%1], 16;" :: "r"(dst), "l"(src))
#define CPCOMMIT()      asm volatile("cp.async.commit_group;")
#define CPWAIT1()       asm volatile("cp.async.wait_group 1;")
#define CPWAIT0()       asm volatile("cp.async.wait_group 0;")

// Scratch (device globals; no allocation allowed)
__device__ float g_Qp[(size_t)BB * LQQ * DD];            // wi*q + wc
__device__ float g_t[BB * LQQ];                          // <q,wq> + bias
__device__ float g_S1[(size_t)BB * LCC * LQQ];           // row-softmax(S)
__device__ float g_St[(size_t)BB * LQQ * LCC];           // raw S^T (logits)
__device__ float g_cpart[4 * BB * LQQ];                  // per-i-block col expsum partials
__device__ float g_inv[BB * LQQ];                        // 1 / col expsum
__device__ float g_C2p[2 * (size_t)BB * LQQ * DD];       // S2^T @ contex (2 K-split partials)

// ---------------------------------------------------------------------------
// K0: Q'[b,j,d] = wi[d]*q[b,j,d] + wc[d];  t[b,j] = <q[b,j], wq> + bias
// ---------------------------------------------------------------------------
__global__ void k0_prep(const float* __restrict__ q,
                        const float* __restrict__ W,
                        const float* __restrict__ bias) {
    const int bj = blockIdx.x;
    const int d  = threadIdx.x;
    const float qv = q[(size_t)bj * DD + d];
    g_Qp[(size_t)bj * DD + d] = fmaf(W[2 * DD + d], qv, W[DD + d]);

    float v = qv * W[d];
    #pragma unroll
    for (int o = 16; o > 0; o >>= 1) v += __shfl_xor_sync(0xffffffffu, v, o);
    __shared__ float red[8];
    if ((threadIdx.x & 31) == 0) red[threadIdx.x >> 5] = v;
    __syncthreads();
    if (threadIdx.x == 0) {
        float s = 0.f;
        #pragma unroll
        for (int i = 0; i < 8; i++) s += red[i];
        g_t[bj] = s + bias[0];
    }
}

// ---------------------------------------------------------------------------
// K1: S = contex @ Q'^T + t via raw-fp32 tf32 mma, 3-stage cp.async pipeline.
// Block 128(i) x 64(j), 256 thr = 8 warps (16x64), K=256. grid=(4, B)
// Outputs: S1 (row softmax), raw S^T (coalesced), col expsum partials.
// ---------------------------------------------------------------------------
__global__ void __launch_bounds__(256, 2) k1_score(const float* __restrict__ contex) {
    const int b  = blockIdx.y;
    const int i0 = blockIdx.x * 128;
    const int tid = threadIdx.x;
    const int warp = tid >> 5, lane = tid & 31;
    const int g = lane >> 2, t = lane & 3;
    const int wm = warp * 16;

    extern __shared__ float sm[];
    float* As   = sm;                 // 3 x 128 x 36 = 13824
    float* Bs   = sm + 13824;         // 3 x 64 x 36  = 6912
    float* ts   = sm + 20736;         // 64
    float* scol = sm + 20800;         // 8 x 64 = 512
    if (tid < 64) ts[tid] = g_t[b * LQQ + tid];

    const float* Cb = contex + (size_t)b * LCC * DD;
    const float* Qp = g_Qp  + (size_t)b * LQQ * DD;

    const int alr = tid >> 1, ako = (tid & 1) * 16;   // A: 4x16B per stage
    const int bjr = tid >> 2, bko = (tid & 3) * 8;    // B: 2x16B per stage
    const unsigned smu = sm2u(sm);

    auto cpStage = [&](int s) {
        const int buf = s % 3;
        const float* ga = &Cb[(size_t)(i0 + alr) * DD + s * 32 + ako];
        unsigned da = smu + (unsigned)((buf * 128 + alr) * 36 + ako) * 4u;
        CPA16(da,      ga);     CPA16(da + 16, ga + 4);
        CPA16(da + 32, ga + 8); CPA16(da + 48, ga + 12);
        const float* gb = &Qp[(size_t)bjr * DD + s * 32 + bko];
        unsigned db = smu + (unsigned)(13824 + (buf * 64 + bjr) * 36 + bko) * 4u;
        CPA16(db, gb); CPA16(db + 16, gb + 4);
        CPCOMMIT();
    };

    float acc[8][4];
    #pragma unroll
    for (int nt = 0; nt < 8; nt++)
        #pragma unroll
        for (int r = 0; r < 4; r++) acc[nt][r] = 0.f;

    cpStage(0); cpStage(1);

    #pragma unroll
    for (int it = 0; it < 8; it++) {
        if (it < 7) { CPWAIT1(); } else { CPWAIT0(); }
        __syncthreads();
        if (it + 2 < 8) cpStage(it + 2);
        const float* Ab = As + (size_t)(it % 3) * 128 * 36;
        const float* Bb = Bs + (size_t)(it % 3) * 64 * 36;
        #pragma unroll
        for (int kc = 0; kc < 32; kc += 8) {
            unsigned a0 = *(const unsigned*)&Ab[(size_t)(wm + g) * 36 + kc + t];
            unsigned a1 = *(const unsigned*)&Ab[(size_t)(wm + 8 + g) * 36 + kc + t];
            unsigned a2 = *(const unsigned*)&Ab[(size_t)(wm + g) * 36 + kc + t + 4];
            unsigned a3 = *(const unsigned*)&Ab[(size_t)(wm + 8 + g) * 36 + kc + t + 4];
            #pragma unroll
            for (int nt = 0; nt < 8; nt++) {
                unsigned b0 = *(const unsigned*)&Bb[(size_t)(nt * 8 + g) * 36 + kc + t];
                unsigned b1 = *(const unsigned*)&Bb[(size_t)(nt * 8 + g) * 36 + kc + t + 4];
                mma8(acc[nt][0], acc[nt][1], acc[nt][2], acc[nt][3],
                     a0, a1, a2, a3, b0, b1);
            }
        }
        __syncthreads();
    }

    // ---- epilogue: +t[j], stage S^T in smem, col expsums, row softmax ----
    float* Ssm = sm;                         // reuse As region: 64 x 132
    float* S1b = g_S1 + (size_t)b * LCC * LQQ;
    float cs[16];
    #pragma unroll
    for (int c = 0; c < 16; c++) cs[c] = 0.f;

    #pragma unroll
    for (int h = 0; h < 2; h++) {
        const int il = wm + h * 8 + g;
        const int i  = i0 + il;
        float s[16];
        #pragma unroll
        for (int nt = 0; nt < 8; nt++) {
            s[2 * nt]     = acc[nt][2 * h]     + ts[nt * 8 + 2 * t];
            s[2 * nt + 1] = acc[nt][2 * h + 1] + ts[nt * 8 + 2 * t + 1];
        }
        #pragma unroll
        for (int c = 0; c < 16; c++) {
            const int j = (c >> 1) * 8 + 2 * t + (c & 1);
            Ssm[(size_t)j * 132 + il] = s[c];
        }
        #pragma unroll
        for (int c = 0; c < 16; c++) cs[c] += expf(s[c]);
        float m = s[0];
        #pragma unroll
        for (int c = 1; c < 16; c++) m = fmaxf(m, s[c]);
        m = fmaxf(m, __shfl_xor_sync(0xffffffffu, m, 1));
        m = fmaxf(m, __shfl_xor_sync(0xffffffffu, m, 2));
        float e[16], sum = 0.f;
        #pragma unroll
        for (int c = 0; c < 16; c++) { e[c] = expf(s[c] - m); sum += e[c]; }
        sum += __shfl_xor_sync(0xffffffffu, sum, 1);
        sum += __shfl_xor_sync(0xffffffffu, sum, 2);
        const float inv = 1.f / sum;
        #pragma unroll
        for (int nt = 0; nt < 8; nt++) {
            float2 o = make_float2(e[2 * nt] * inv, e[2 * nt + 1] * inv);
            *(float2*)&S1b[(size_t)i * LQQ + nt * 8 + 2 * t] = o;
        }
    }
    #pragma unroll
    for (int c = 0; c < 16; c++) {
        cs[c] += __shfl_xor_sync(0xffffffffu, cs[c], 4);
        cs[c] += __shfl_xor_sync(0xffffffffu, cs[c], 8);
        cs[c] += __shfl_xor_sync(0xffffffffu, cs[c], 16);
    }
    if (g == 0) {
        #pragma unroll
        for (int c = 0; c < 16; c++) {
            const int j = (c >> 1) * 8 + 2 * t + (c & 1);
            scol[warp * 64 + j] = cs[c];
        }
    }
    __syncthreads();

    {   // coalesced raw S^T write: 64 rows x 128 cols
        const int r = tid >> 2, co = (tid & 3) * 32;
        float* dst = &g_St[((size_t)b * LQQ + r) * LCC + i0 + co];
        const float* src = &Ssm[(size_t)r * 132 + co];
        #pragma unroll
        for (int u = 0; u < 8; u++)
            *(float4*)&dst[u * 4] = *(const float4*)&src[u * 4];
    }
    if (tid < 64) {
        float p = 0.f;
        #pragma unroll
        for (int w = 0; w < 8; w++) p += scol[w * 64 + tid];
        g_cpart[blockIdx.x * (BB * LQQ) + b * LQQ + tid] = p;
    }
}

// ---------------------------------------------------------------------------
// K2c: combine 4 partials -> inv. grid=(B), 64 thr.
// ---------------------------------------------------------------------------
__global__ void k2c_inv() {
    const int idx = blockIdx.x * LQQ + threadIdx.x;
    float s = g_cpart[idx] + g_cpart[BB * LQQ + idx]
            + g_cpart[2 * BB * LQQ + idx] + g_cpart[3 * BB * LQQ + idx];
    g_inv[idx] = 1.f / s;
}

// ---------------------------------------------------------------------------
// K3: C2 = S2^T @ contex; S2 = exp(rawSt)*inv applied on A-fill (reg 2-stage);
// contex B-tile via 3-stage cp.async. Block 64(j) x 128(d), K split 2.
// 256 thr = 8 warps 2(m)x4(n), 32x32 tiles. grid=(2, B, 2)
// ---------------------------------------------------------------------------
__global__ void __launch_bounds__(256, 2) k3_c2(const float* __restrict__ contex) {
    const int b   = blockIdx.y;
    const int n0  = blockIdx.x * 128;
    const int kk0 = blockIdx.z * 256;
    const int tid = threadIdx.x;
    const int warp = tid >> 5, lane = tid & 31;
    const int g = lane >> 2, t = lane & 3;
    const int wm = (warp & 1) * 32;
    const int wn = (warp >> 1) * 32;

    extern __shared__ float sm3[];
    float* As = sm3;                        // 2 x 64 x 36  [j][k]   (reg-staged exp)
    float* Bs = sm3 + 2 * 64 * 36;          // 3 x 32 x 136 [k][n]   (cp.async)

    const float* S2t = g_St + (size_t)b * LQQ * LCC;
    const float* Cb  = contex + (size_t)b * LCC * DD;

    const int ajr = tid >> 2, ako = (tid & 3) * 8;    // A: 2x float4
    const int bkr = tid >> 3, bnc = (tid & 7) * 16;   // B: 4x16B cp.async
    const float invj = g_inv[b * LQQ + ajr];
    const unsigned smu = sm2u(sm3);

    auto cpB = [&](int s) {
        const int buf = s % 3;
        const float* c = &Cb[(size_t)(kk0 + s * 32 + bkr) * DD + n0 + bnc];
        unsigned db = smu + (unsigned)(2 * 64 * 36 + (buf * 32 + bkr) * 136 + bnc) * 4u;
        CPA16(db, c); CPA16(db + 16, c + 4); CPA16(db + 32, c + 8); CPA16(db + 48, c + 12);
        CPCOMMIT();
    };

    float4 ra[2];
    auto ldA = [&](int s) {
        const float* p = &S2t[(size_t)ajr * LCC + kk0 + s * 32 + ako];
        ra[0] = *(const float4*)&p[0]; ra[1] = *(const float4*)&p[4];
    };
    auto stA = [&](int s) {
        float* da = &As[(size_t)((s & 1) * 64 + ajr) * 36 + ako];
        da[0] = expf(ra[0].x) * invj; da[1] = expf(ra[0].y) * invj;
        da[2] = expf(ra[0].z) * invj; da[3] = expf(ra[0].w) * invj;
        da[4] = expf(ra[1].x) * invj; da[5] = expf(ra[1].y) * invj;
        da[6] = expf(ra[1].z) * invj; da[7] = expf(ra[1].w) * invj;
    };

    float acc[2][4][4];
    #pragma unroll
    for (int mt = 0; mt < 2; mt++)
        #pragma unroll
        for (int nt = 0; nt < 4; nt++)
            #pragma unroll
            for (int r = 0; r < 4; r++) acc[mt][nt][r] = 0.f;

    cpB(0); cpB(1);
    ldA(0); stA(0);

    #pragma unroll
    for (int it = 0; it < 8; it++) {
        if (it < 7) { CPWAIT1(); } else { CPWAIT0(); }
        __syncthreads();
        if (it + 2 < 8) cpB(it + 2);
        if (it < 7) ldA(it + 1);

        const float* Ab = As + (size_t)(it & 1) * 64 * 36;
        const float* Bb = Bs + (size_t)(it % 3) * 32 * 136;
        #pragma unroll
        for (int kc = 0; kc < 32; kc += 8) {
            unsigned a[2][4];
            #pragma unroll
            for (int mt = 0; mt < 2; mt++) {
                const int r = wm + mt * 16 + g;
                a[mt][0] = *(const unsigned*)&Ab[(size_t)r * 36 + kc + t];
                a[mt][1] = *(const unsigned*)&Ab[(size_t)(r + 8) * 36 + kc + t];
                a[mt][2] = *(const unsigned*)&Ab[(size_t)r * 36 + kc + t + 4];
                a[mt][3] = *(const unsigned*)&Ab[(size_t)(r + 8) * 36 + kc + t + 4];
            }
            #pragma unroll
            for (int nt = 0; nt < 4; nt++) {
                const int n = wn + nt * 8 + g;
                unsigned b0 = *(const unsigned*)&Bb[(size_t)(kc + t) * 136 + n];
                unsigned b1 = *(const unsigned*)&Bb[(size_t)(kc + t + 4) * 136 + n];
                mma8(acc[0][nt][0], acc[0][nt][1], acc[0][nt][2], acc[0][nt][3],
                     a[0][0], a[0][1], a[0][2], a[0][3], b0, b1);
                mma8(acc[1][nt][0], acc[1][nt][1], acc[1][nt][2], acc[1][nt][3],
                     a[1][0], a[1][1], a[1][2], a[1][3], b0, b1);
            }
        }
        if (it < 7) stA(it + 1);
        __syncthreads();
    }

    float* outp = g_C2p + (size_t)blockIdx.z * BB * LQQ * DD + (size_t)b * LQQ * DD;
    #pragma unroll
    for (int mt = 0; mt < 2; mt++)
        #pragma unroll
        for (int h = 0; h < 2; h++) {
            const int j = wm + mt * 16 + h * 8 + g;
            #pragma unroll
            for (int nt = 0; nt < 4; nt++) {
                float2 o = make_float2(acc[mt][nt][2 * h], acc[mt][nt][2 * h + 1]);
                *(float2*)&outp[(size_t)j * DD + n0 + wn + nt * 8 + 2 * t] = o;
            }
        }
}

// ---------------------------------------------------------------------------
// K4: A = S1 @ question, Bm = S1 @ (C2p0+C2p1), dual-B per chunk (4 chunks),
// fused output: out[b,i] = [contex | A | contex*A | contex*Bm]
// Block 128(i), 256 thr = 8 warps (16x64). Raw fp32 operands. grid=(4, B)
// ---------------------------------------------------------------------------
__global__ void __launch_bounds__(256) k4_out(const float* __restrict__ contex,
                                              const float* __restrict__ question,
                                              float* __restrict__ out) {
    const int b  = blockIdx.y;
    const int i0 = blockIdx.x * 128;
    const int tid = threadIdx.x;
    const int warp = tid >> 5, lane = tid & 31;
    const int g = lane >> 2, t = lane & 3;
    const int wm = warp * 16;

    extern __shared__ float sm4[];
    float* As = sm4;                        // 128 x 68 [i][j] persistent
    float* Bt = sm4 + 128 * 68;             // 2 buf x 2 tiles x 64 x 72

    const float* S1b = g_S1 + (size_t)b * LCC * LQQ;
    {   // fill A once (raw fp32)
        const int lr = tid >> 1, jo = (tid & 1) * 32;
        const float* src = &S1b[(size_t)(i0 + lr) * LQQ + jo];
        float* dst = &As[(size_t)lr * 68 + jo];
        #pragma unroll
        for (int u = 0; u < 8; u++) *(float4*)&dst[u * 4] = *(const float4*)&src[u * 4];
    }

    const float* Cb = contex   + (size_t)b * LCC * DD;
    const float* Qb = question + (size_t)b * LQQ * DD;
    const float* P0 = g_C2p    + (size_t)b * LQQ * DD;
    const float* P1 = g_C2p + (size_t)BB * LQQ * DD + (size_t)b * LQQ * DD;
    float* outb = out + (size_t)b * LCC * 1024;

    const int bjr = tid >> 2, boff = (tid & 3) * 16;
    float4 rq[4], rc[4];

    auto ldB = [&](int chunk) {
        const int c0 = chunk * 64;
        const float* src = &Qb[(size_t)bjr * DD + c0 + boff];
        rq[0] = *(const float4*)&src[0];  rq[1] = *(const float4*)&src[4];
        rq[2] = *(const float4*)&src[8];  rq[3] = *(const float4*)&src[12];
        const float* s0 = &P0[(size_t)bjr * DD + c0 + boff];
        const float* s1 = &P1[(size_t)bjr * DD + c0 + boff];
        #pragma unroll
        for (int u = 0; u < 4; u++) {
            float4 x = *(const float4*)&s0[u * 4];
            float4 y = *(const float4*)&s1[u * 4];
            rc[u] = make_float4(x.x + y.x, x.y + y.y, x.z + y.z, x.w + y.w);
        }
    };
    auto stB = [&](int buf) {
        float* dq = &Bt[((size_t)buf * 128 + bjr) * 72 + boff];
        *(float4*)&dq[0] = rq[0]; *(float4*)&dq[4] = rq[1];
        *(float4*)&dq[8] = rq[2]; *(float4*)&dq[12] = rq[3];
        float* dc = &Bt[((size_t)buf * 128 + 64 + bjr) * 72 + boff];
        *(float4*)&dc[0] = rc[0]; *(float4*)&dc[4] = rc[1];
        *(float4*)&dc[8] = rc[2]; *(float4*)&dc[12] = rc[3];
    };

    ldB(0); stB(0);
    __syncthreads();

    #pragma unroll
    for (int chunk = 0; chunk < 4; chunk++) {
        const int buf = chunk & 1;
        const int c0 = chunk * 64;
        if (chunk < 3) ldB(chunk + 1);

        float accq[8][4], accc[8][4];
        #pragma unroll
        for (int nt = 0; nt < 8; nt++)
            #pragma unroll
            for (int r = 0; r < 4; r++) { accq[nt][r] = 0.f; accc[nt][r] = 0.f; }

        const float* Bq = Bt + (size_t)buf * 128 * 72;
        const float* Bc = Bq + 64 * 72;
        #pragma unroll
        for (int kc = 0; kc < 64; kc += 8) {
            unsigned a0 = *(const unsigned*)&As[(size_t)(wm + g) * 68 + kc + t];
            unsigned a1 = *(const unsigned*)&As[(size_t)(wm + 8 + g) * 68 + kc + t];
            unsigned a2 = *(const unsigned*)&As[(size_t)(wm + g) * 68 + kc + t + 4];
            unsigned a3 = *(const unsigned*)&As[(size_t)(wm + 8 + g) * 68 + kc + t + 4];
            #pragma unroll
            for (int nt = 0; nt < 8; nt++) {
                const int n = nt * 8 + g;
                unsigned q0 = *(const unsigned*)&Bq[(size_t)(kc + t) * 72 + n];
                unsigned q1 = *(const unsigned*)&Bq[(size_t)(kc + t + 4) * 72 + n];
                mma8(accq[nt][0], accq[nt][1], accq[nt][2], accq[nt][3],
                     a0, a1, a2, a3, q0, q1);
                unsigned c0r = *(const unsigned*)&Bc[(size_t)(kc + t) * 72 + n];
                unsigned c1r = *(const unsigned*)&Bc[(size_t)(kc + t + 4) * 72 + n];
                mma8(accc[nt][0], accc[nt][1], accc[nt][2], accc[nt][3],
                     a0, a1, a2, a3, c0r, c1r);
            }
        }

        #pragma unroll
        for (int h = 0; h < 2; h++) {
            const int i = i0 + wm + h * 8 + g;
            const float* crow = &Cb[(size_t)i * DD];
            float* orow = &outb[(size_t)i * 1024];
            #pragma unroll
            for (int nt = 0; nt < 8; nt++) {
                const int col = c0 + nt * 8 + 2 * t;
                float2 cv = *(const float2*)&crow[col];
                float2 av = make_float2(accq[nt][2 * h], accq[nt][2 * h + 1]);
                float2 bv = make_float2(accc[nt][2 * h], accc[nt][2 * h + 1]);
                float2 pa = make_float2(cv.x * av.x, cv.y * av.y);
                float2 pb = make_float2(cv.x * bv.x, cv.y * bv.y);
                *(float2*)&orow[col]       = cv;
                *(float2*)&orow[256 + col] = av;
                *(float2*)&orow[512 + col] = pa;
                *(float2*)&orow[768 + col] = pb;
            }
        }

        if (chunk < 3) stB(buf ^ 1);
        __syncthreads();
    }
}

// ---------------------------------------------------------------------------
extern "C" void kernel_launch(void* const* d_in, const int* in_sizes, int n_in,
                              void* d_out, int out_size) {
    const float* contex   = (const float*)d_in[0];
    const float* question = (const float*)d_in[1];
    const float* W        = (const float*)d_in[2];
    const float* bias     = (const float*)d_in[3];
    float* out = (float*)d_out;

    const int k1smem = 21312 * (int)sizeof(float);                          // 85248
    const int k3smem = (2 * 64 * 36 + 3 * 32 * 136) * (int)sizeof(float);   // 70656
    const int k4smem = (128 * 68 + 2 * 2 * 64 * 72) * (int)sizeof(float);   // 108544
    cudaFuncSetAttribute(k1_score, cudaFuncAttributeMaxDynamicSharedMemorySize, k1smem);
    cudaFuncSetAttribute(k3_c2,    cudaFuncAttributeMaxDynamicSharedMemorySize, k3smem);
    cudaFuncSetAttribute(k4_out,   cudaFuncAttributeMaxDynamicSharedMemorySize, k4smem);

    k0_prep<<<BB * LQQ, 256>>>(question, W, bias);
    k1_score<<<dim3(4, BB), 256, k1smem>>>(contex);
    k2c_inv<<<BB, LQQ>>>();
    k3_c2<<<dim3(2, BB, 2), 256, k3smem>>>(contex);
    k4_out<<<dim3(4, BB), 256, k4smem>>>(contex, question, out);
}

// round 8
// speedup vs baseline: 2.7705x; 1.0340x over previous
#include <cuda_runtime.h>
#include <math.h>

#define BB  64
#define LCC 512
#define LQQ 64
#define DD  256

// ---------------------------------------------------------------------------
// tf32 mma (m16n8k8, row.col, fp32 accum) — operands are RAW fp32 bits
// ---------------------------------------------------------------------------
__device__ __forceinline__ void mma8(float& d0, float& d1, float& d2, float& d3,
                                     unsigned a0, unsigned a1, unsigned a2, unsigned a3,
                                     unsigned b0, unsigned b1) {
    asm("mma.sync.aligned.m16n8k8.row.col.f32.tf32.tf32.f32 "
        "{%0,%1,%2,%3},{%4,%5,%6,%7},{%8,%9},{%0,%1,%2,%3};"
        : "+f"(d0), "+f"(d1), "+f"(d2), "+f"(d3)
        : "r"(a0), "r"(a1), "r"(a2), "r"(a3), "r"(b0), "r"(b1));
}
__device__ __forceinline__ unsigned sm2u(const void* p) {
    unsigned r;
    asm("{.reg .u64 t; cvta.to.shared.u64 t, %1; cvt.u32.u64 %0, t;}" : "=r"(r) : "l"(p));
    return r;
}
#define CPA16(dst, src) asm volatile("cp.async.ca.shared.global [%0], [%1], 16;" :: "r"(dst), "l"(src))
#define CPCOMMIT()      asm volatile("cp.async.commit_group;")
#define CPWAIT1()       asm volatile("cp.async.wait_group 1;")
#define CPWAIT0()       asm volatile("cp.async.wait_group 0;")

// Scratch (device globals; no allocation allowed)
__device__ float g_Qp[(size_t)BB * LQQ * DD];            // wi*q + wc
__device__ float g_t[BB * LQQ];                          // <q,wq> + bias
__device__ float g_S1[(size_t)BB * LCC * LQQ];           // row-softmax(S)
__device__ float g_St[(size_t)BB * LQQ * LCC];           // raw S^T (logits)
__device__ float g_cpart[4 * BB * LQQ];                  // per-i-block col expsum partials
__device__ float g_inv[BB * LQQ];                        // 1 / col expsum
__device__ float g_C2[(size_t)BB * LQQ * DD];            // S2^T @ contex

// ---------------------------------------------------------------------------
// K0: Q'[b,j,d] = wi[d]*q[b,j,d] + wc[d];  t[b,j] = <q[b,j], wq> + bias
// ---------------------------------------------------------------------------
__global__ void k0_prep(const float* __restrict__ q,
                        const float* __restrict__ W,
                        const float* __restrict__ bias) {
    const int bj = blockIdx.x;
    const int d  = threadIdx.x;
    const float qv = q[(size_t)bj * DD + d];
    g_Qp[(size_t)bj * DD + d] = fmaf(W[2 * DD + d], qv, W[DD + d]);

    float v = qv * W[d];
    #pragma unroll
    for (int o = 16; o > 0; o >>= 1) v += __shfl_xor_sync(0xffffffffu, v, o);
    __shared__ float red[8];
    if ((threadIdx.x & 31) == 0) red[threadIdx.x >> 5] = v;
    __syncthreads();
    if (threadIdx.x == 0) {
        float s = 0.f;
        #pragma unroll
        for (int i = 0; i < 8; i++) s += red[i];
        g_t[bj] = s + bias[0];
    }
}

// ---------------------------------------------------------------------------
// K1: S = contex @ Q'^T + t via raw-fp32 tf32 mma, 3-stage cp.async pipeline.
// Block 128(i) x 64(j), 256 thr = 8 warps (16x64), K=256. grid=(4, B)
// Outputs: S1 (row softmax), raw S^T (coalesced), col expsum partials.
// ---------------------------------------------------------------------------
__global__ void __launch_bounds__(256, 2) k1_score(const float* __restrict__ contex) {
    const int b  = blockIdx.y;
    const int i0 = blockIdx.x * 128;
    const int tid = threadIdx.x;
    const int warp = tid >> 5, lane = tid & 31;
    const int g = lane >> 2, t = lane & 3;
    const int wm = warp * 16;

    extern __shared__ float sm[];
    float* As   = sm;                 // 3 x 128 x 36 = 13824
    float* Bs   = sm + 13824;         // 3 x 64 x 36  = 6912
    float* ts   = sm + 20736;         // 64
    float* scol = sm + 20800;         // 8 x 64 = 512
    if (tid < 64) ts[tid] = g_t[b * LQQ + tid];

    const float* Cb = contex + (size_t)b * LCC * DD;
    const float* Qp = g_Qp  + (size_t)b * LQQ * DD;

    const int alr = tid >> 1, ako = (tid & 1) * 16;   // A: 4x16B per stage
    const int bjr = tid >> 2, bko = (tid & 3) * 8;    // B: 2x16B per stage
    const unsigned smu = sm2u(sm);

    auto cpStage = [&](int s) {
        const int buf = s % 3;
        const float* ga = &Cb[(size_t)(i0 + alr) * DD + s * 32 + ako];
        unsigned da = smu + (unsigned)((buf * 128 + alr) * 36 + ako) * 4u;
        CPA16(da,      ga);     CPA16(da + 16, ga + 4);
        CPA16(da + 32, ga + 8); CPA16(da + 48, ga + 12);
        const float* gb = &Qp[(size_t)bjr * DD + s * 32 + bko];
        unsigned db = smu + (unsigned)(13824 + (buf * 64 + bjr) * 36 + bko) * 4u;
        CPA16(db, gb); CPA16(db + 16, gb + 4);
        CPCOMMIT();
    };

    float acc[8][4];
    #pragma unroll
    for (int nt = 0; nt < 8; nt++)
        #pragma unroll
        for (int r = 0; r < 4; r++) acc[nt][r] = 0.f;

    cpStage(0); cpStage(1);

    #pragma unroll
    for (int it = 0; it < 8; it++) {
        if (it < 7) { CPWAIT1(); } else { CPWAIT0(); }
        __syncthreads();
        if (it + 2 < 8) cpStage(it + 2);
        const float* Ab = As + (size_t)(it % 3) * 128 * 36;
        const float* Bb = Bs + (size_t)(it % 3) * 64 * 36;
        #pragma unroll
        for (int kc = 0; kc < 32; kc += 8) {
            unsigned a0 = *(const unsigned*)&Ab[(size_t)(wm + g) * 36 + kc + t];
            unsigned a1 = *(const unsigned*)&Ab[(size_t)(wm + 8 + g) * 36 + kc + t];
            unsigned a2 = *(const unsigned*)&Ab[(size_t)(wm + g) * 36 + kc + t + 4];
            unsigned a3 = *(const unsigned*)&Ab[(size_t)(wm + 8 + g) * 36 + kc + t + 4];
            #pragma unroll
            for (int nt = 0; nt < 8; nt++) {
                unsigned b0 = *(const unsigned*)&Bb[(size_t)(nt * 8 + g) * 36 + kc + t];
                unsigned b1 = *(const unsigned*)&Bb[(size_t)(nt * 8 + g) * 36 + kc + t + 4];
                mma8(acc[nt][0], acc[nt][1], acc[nt][2], acc[nt][3],
                     a0, a1, a2, a3, b0, b1);
            }
        }
        __syncthreads();
    }

    // ---- epilogue: +t[j], stage S^T in smem, col expsums, row softmax ----
    float* Ssm = sm;                         // reuse As region: 64 x 132
    float* S1b = g_S1 + (size_t)b * LCC * LQQ;
    float cs[16];
    #pragma unroll
    for (int c = 0; c < 16; c++) cs[c] = 0.f;

    #pragma unroll
    for (int h = 0; h < 2; h++) {
        const int il = wm + h * 8 + g;
        const int i  = i0 + il;
        float s[16];
        #pragma unroll
        for (int nt = 0; nt < 8; nt++) {
            s[2 * nt]     = acc[nt][2 * h]     + ts[nt * 8 + 2 * t];
            s[2 * nt + 1] = acc[nt][2 * h + 1] + ts[nt * 8 + 2 * t + 1];
        }
        #pragma unroll
        for (int c = 0; c < 16; c++) {
            const int j = (c >> 1) * 8 + 2 * t + (c & 1);
            Ssm[(size_t)j * 132 + il] = s[c];
        }
        #pragma unroll
        for (int c = 0; c < 16; c++) cs[c] += __expf(s[c]);
        float m = s[0];
        #pragma unroll
        for (int c = 1; c < 16; c++) m = fmaxf(m, s[c]);
        m = fmaxf(m, __shfl_xor_sync(0xffffffffu, m, 1));
        m = fmaxf(m, __shfl_xor_sync(0xffffffffu, m, 2));
        float e[16], sum = 0.f;
        #pragma unroll
        for (int c = 0; c < 16; c++) { e[c] = __expf(s[c] - m); sum += e[c]; }
        sum += __shfl_xor_sync(0xffffffffu, sum, 1);
        sum += __shfl_xor_sync(0xffffffffu, sum, 2);
        const float inv = 1.f / sum;
        #pragma unroll
        for (int nt = 0; nt < 8; nt++) {
            float2 o = make_float2(e[2 * nt] * inv, e[2 * nt + 1] * inv);
            *(float2*)&S1b[(size_t)i * LQQ + nt * 8 + 2 * t] = o;
        }
    }
    #pragma unroll
    for (int c = 0; c < 16; c++) {
        cs[c] += __shfl_xor_sync(0xffffffffu, cs[c], 4);
        cs[c] += __shfl_xor_sync(0xffffffffu, cs[c], 8);
        cs[c] += __shfl_xor_sync(0xffffffffu, cs[c], 16);
    }
    if (g == 0) {
        #pragma unroll
        for (int c = 0; c < 16; c++) {
            const int j = (c >> 1) * 8 + 2 * t + (c & 1);
            scol[warp * 64 + j] = cs[c];
        }
    }
    __syncthreads();

    {   // coalesced raw S^T write: 64 rows x 128 cols
        const int r = tid >> 2, co = (tid & 3) * 32;
        float* dst = &g_St[((size_t)b * LQQ + r) * LCC + i0 + co];
        const float* src = &Ssm[(size_t)r * 132 + co];
        #pragma unroll
        for (int u = 0; u < 8; u++)
            *(float4*)&dst[u * 4] = *(const float4*)&src[u * 4];
    }
    if (tid < 64) {
        float p = 0.f;
        #pragma unroll
        for (int w = 0; w < 8; w++) p += scol[w * 64 + tid];
        g_cpart[blockIdx.x * (BB * LQQ) + b * LQQ + tid] = p;
    }
}

// ---------------------------------------------------------------------------
// K2c: combine 4 partials -> inv. grid=(B), 64 thr.
// ---------------------------------------------------------------------------
__global__ void k2c_inv() {
    const int idx = blockIdx.x * LQQ + threadIdx.x;
    float s = g_cpart[idx] + g_cpart[BB * LQQ + idx]
            + g_cpart[2 * BB * LQQ + idx] + g_cpart[3 * BB * LQQ + idx];
    g_inv[idx] = 1.f / s;
}

// ---------------------------------------------------------------------------
// K3: C2 = S2^T @ contex, FULL K=512 per block (no partials).
// S2 = __expf(rawSt)*inv applied on A-fill (reg 2-stage); B via 3-stage cp.async.
// Block 64(j) x 64(n), 256 thr = 8 warps 4(m)x2(n), warp tile 16x32.
// grid=(4, B), 3 blocks/SM target.
// ---------------------------------------------------------------------------
__global__ void __launch_bounds__(256, 3) k3_c2(const float* __restrict__ contex) {
    const int b   = blockIdx.y;
    const int n0  = blockIdx.x * 64;
    const int tid = threadIdx.x;
    const int warp = tid >> 5, lane = tid & 31;
    const int g = lane >> 2, t = lane & 3;
    const int wm = (warp & 3) * 16;
    const int wn = (warp >> 2) * 32;

    extern __shared__ float sm3[];
    float* As = sm3;                        // 2 x 64 x 36 [j][k]   (reg-staged exp)
    float* Bs = sm3 + 2 * 64 * 36;          // 3 x 32 x 72 [k][n]   (cp.async)

    const float* S2t = g_St + (size_t)b * LQQ * LCC;
    const float* Cb  = contex + (size_t)b * LCC * DD;

    const int ajr = tid >> 2, ako = (tid & 3) * 8;    // A: 2x float4
    const int bkr = tid >> 3, bnc = (tid & 7) * 8;    // B: 2x16B cp.async
    const float invj = g_inv[b * LQQ + ajr];
    const unsigned smu = sm2u(sm3);

    auto cpB = [&](int s) {
        const int buf = s % 3;
        const float* c = &Cb[(size_t)(s * 32 + bkr) * DD + n0 + bnc];
        unsigned db = smu + (unsigned)(2 * 64 * 36 + (buf * 32 + bkr) * 72 + bnc) * 4u;
        CPA16(db, c); CPA16(db + 16, c + 4);
        CPCOMMIT();
    };

    float4 ra[2];
    auto ldA = [&](int s) {
        const float* p = &S2t[(size_t)ajr * LCC + s * 32 + ako];
        ra[0] = *(const float4*)&p[0]; ra[1] = *(const float4*)&p[4];
    };
    auto stA = [&](int s) {
        float* da = &As[(size_t)((s & 1) * 64 + ajr) * 36 + ako];
        da[0] = __expf(ra[0].x) * invj; da[1] = __expf(ra[0].y) * invj;
        da[2] = __expf(ra[0].z) * invj; da[3] = __expf(ra[0].w) * invj;
        da[4] = __expf(ra[1].x) * invj; da[5] = __expf(ra[1].y) * invj;
        da[6] = __expf(ra[1].z) * invj; da[7] = __expf(ra[1].w) * invj;
    };

    float acc[4][4];
    #pragma unroll
    for (int nt = 0; nt < 4; nt++)
        #pragma unroll
        for (int r = 0; r < 4; r++) acc[nt][r] = 0.f;

    cpB(0); cpB(1);
    ldA(0); stA(0);

    #pragma unroll 4
    for (int it = 0; it < 16; it++) {
        if (it < 15) { CPWAIT1(); } else { CPWAIT0(); }
        __syncthreads();
        if (it + 2 < 16) cpB(it + 2);
        if (it < 15) ldA(it + 1);

        const float* Ab = As + (size_t)(it & 1) * 64 * 36;
        const float* Bb = Bs + (size_t)(it % 3) * 32 * 72;
        #pragma unroll
        for (int kc = 0; kc < 32; kc += 8) {
            unsigned a0 = *(const unsigned*)&Ab[(size_t)(wm + g) * 36 + kc + t];
            unsigned a1 = *(const unsigned*)&Ab[(size_t)(wm + 8 + g) * 36 + kc + t];
            unsigned a2 = *(const unsigned*)&Ab[(size_t)(wm + g) * 36 + kc + t + 4];
            unsigned a3 = *(const unsigned*)&Ab[(size_t)(wm + 8 + g) * 36 + kc + t + 4];
            #pragma unroll
            for (int nt = 0; nt < 4; nt++) {
                const int n = wn + nt * 8 + g;
                unsigned b0 = *(const unsigned*)&Bb[(size_t)(kc + t) * 72 + n];
                unsigned b1 = *(const unsigned*)&Bb[(size_t)(kc + t + 4) * 72 + n];
                mma8(acc[nt][0], acc[nt][1], acc[nt][2], acc[nt][3],
                     a0, a1, a2, a3, b0, b1);
            }
        }
        if (it < 15) stA(it + 1);
        __syncthreads();
    }

    float* outp = g_C2 + (size_t)b * LQQ * DD;
    #pragma unroll
    for (int h = 0; h < 2; h++) {
        const int j = wm + h * 8 + g;
        #pragma unroll
        for (int nt = 0; nt < 4; nt++) {
            float2 o = make_float2(acc[nt][2 * h], acc[nt][2 * h + 1]);
            *(float2*)&outp[(size_t)j * DD + n0 + wn + nt * 8 + 2 * t] = o;
        }
    }
}

// ---------------------------------------------------------------------------
// K4: A = S1 @ question, Bm = S1 @ C2, dual-B per chunk (4 chunks),
// fused output: out[b,i] = [contex | A | contex*A | contex*Bm]
// Block 128(i), 256 thr = 8 warps (16x64). Raw fp32 operands. grid=(4, B)
// ---------------------------------------------------------------------------
__global__ void __launch_bounds__(256) k4_out(const float* __restrict__ contex,
                                              const float* __restrict__ question,
                                              float* __restrict__ out) {
    const int b  = blockIdx.y;
    const int i0 = blockIdx.x * 128;
    const int tid = threadIdx.x;
    const int warp = tid >> 5, lane = tid & 31;
    const int g = lane >> 2, t = lane & 3;
    const int wm = warp * 16;

    extern __shared__ float sm4[];
    float* As = sm4;                        // 128 x 68 [i][j] persistent
    float* Bt = sm4 + 128 * 68;             // 2 buf x 2 tiles x 64 x 72

    const float* S1b = g_S1 + (size_t)b * LCC * LQQ;
    {   // fill A once (raw fp32)
        const int lr = tid >> 1, jo = (tid & 1) * 32;
        const float* src = &S1b[(size_t)(i0 + lr) * LQQ + jo];
        float* dst = &As[(size_t)lr * 68 + jo];
        #pragma unroll
        for (int u = 0; u < 8; u++) *(float4*)&dst[u * 4] = *(const float4*)&src[u * 4];
    }

    const float* Cb = contex   + (size_t)b * LCC * DD;
    const float* Qb = question + (size_t)b * LQQ * DD;
    const float* P  = g_C2     + (size_t)b * LQQ * DD;
    float* outb = out + (size_t)b * LCC * 1024;

    const int bjr = tid >> 2, boff = (tid & 3) * 16;
    float4 rq[4], rc[4];

    auto ldB = [&](int chunk) {
        const int c0 = chunk * 64;
        const float* src = &Qb[(size_t)bjr * DD + c0 + boff];
        rq[0] = *(const float4*)&src[0];  rq[1] = *(const float4*)&src[4];
        rq[2] = *(const float4*)&src[8];  rq[3] = *(const float4*)&src[12];
        const float* s0 = &P[(size_t)bjr * DD + c0 + boff];
        rc[0] = *(const float4*)&s0[0];  rc[1] = *(const float4*)&s0[4];
        rc[2] = *(const float4*)&s0[8];  rc[3] = *(const float4*)&s0[12];
    };
    auto stB = [&](int buf) {
        float* dq = &Bt[((size_t)buf * 128 + bjr) * 72 + boff];
        *(float4*)&dq[0] = rq[0]; *(float4*)&dq[4] = rq[1];
        *(float4*)&dq[8] = rq[2]; *(float4*)&dq[12] = rq[3];
        float* dc = &Bt[((size_t)buf * 128 + 64 + bjr) * 72 + boff];
        *(float4*)&dc[0] = rc[0]; *(float4*)&dc[4] = rc[1];
        *(float4*)&dc[8] = rc[2]; *(float4*)&dc[12] = rc[3];
    };

    ldB(0); stB(0);
    __syncthreads();

    #pragma unroll
    for (int chunk = 0; chunk < 4; chunk++) {
        const int buf = chunk & 1;
        const int c0 = chunk * 64;
        if (chunk < 3) ldB(chunk + 1);

        float accq[8][4], accc[8][4];
        #pragma unroll
        for (int nt = 0; nt < 8; nt++)
            #pragma unroll
            for (int r = 0; r < 4; r++) { accq[nt][r] = 0.f; accc[nt][r] = 0.f; }

        const float* Bq = Bt + (size_t)buf * 128 * 72;
        const float* Bc = Bq + 64 * 72;
        #pragma unroll
        for (int kc = 0; kc < 64; kc += 8) {
            unsigned a0 = *(const unsigned*)&As[(size_t)(wm + g) * 68 + kc + t];
            unsigned a1 = *(const unsigned*)&As[(size_t)(wm + 8 + g) * 68 + kc + t];
            unsigned a2 = *(const unsigned*)&As[(size_t)(wm + g) * 68 + kc + t + 4];
            unsigned a3 = *(const unsigned*)&As[(size_t)(wm + 8 + g) * 68 + kc + t + 4];
            #pragma unroll
            for (int nt = 0; nt < 8; nt++) {
                const int n = nt * 8 + g;
                unsigned q0 = *(const unsigned*)&Bq[(size_t)(kc + t) * 72 + n];
                unsigned q1 = *(const unsigned*)&Bq[(size_t)(kc + t + 4) * 72 + n];
                mma8(accq[nt][0], accq[nt][1], accq[nt][2], accq[nt][3],
                     a0, a1, a2, a3, q0, q1);
                unsigned c0r = *(const unsigned*)&Bc[(size_t)(kc + t) * 72 + n];
                unsigned c1r = *(const unsigned*)&Bc[(size_t)(kc + t + 4) * 72 + n];
                mma8(accc[nt][0], accc[nt][1], accc[nt][2], accc[nt][3],
                     a0, a1, a2, a3, c0r, c1r);
            }
        }

        #pragma unroll
        for (int h = 0; h < 2; h++) {
            const int i = i0 + wm + h * 8 + g;
            const float* crow = &Cb[(size_t)i * DD];
            float* orow = &outb[(size_t)i * 1024];
            #pragma unroll
            for (int nt = 0; nt < 8; nt++) {
                const int col = c0 + nt * 8 + 2 * t;
                float2 cv = *(const float2*)&crow[col];
                float2 av = make_float2(accq[nt][2 * h], accq[nt][2 * h + 1]);
                float2 bv = make_float2(accc[nt][2 * h], accc[nt][2 * h + 1]);
                float2 pa = make_float2(cv.x * av.x, cv.y * av.y);
                float2 pb = make_float2(cv.x * bv.x, cv.y * bv.y);
                *(float2*)&orow[col]       = cv;
                *(float2*)&orow[256 + col] = av;
                *(float2*)&orow[512 + col] = pa;
                *(float2*)&orow[768 + col] = pb;
            }
        }

        if (chunk < 3) stB(buf ^ 1);
        __syncthreads();
    }
}

// ---------------------------------------------------------------------------
extern "C" void kernel_launch(void* const* d_in, const int* in_sizes, int n_in,
                              void* d_out, int out_size) {
    const float* contex   = (const float*)d_in[0];
    const float* question = (const float*)d_in[1];
    const float* W        = (const float*)d_in[2];
    const float* bias     = (const float*)d_in[3];
    float* out = (float*)d_out;

    const int k1smem = 21312 * (int)sizeof(float);                          // 85248
    const int k3smem = (2 * 64 * 36 + 3 * 32 * 72) * (int)sizeof(float);    // 46080
    const int k4smem = (128 * 68 + 2 * 2 * 64 * 72) * (int)sizeof(float);   // 108544
    cudaFuncSetAttribute(k1_score, cudaFuncAttributeMaxDynamicSharedMemorySize, k1smem);
    cudaFuncSetAttribute(k3_c2,    cudaFuncAttributeMaxDynamicSharedMemorySize, k3smem);
    cudaFuncSetAttribute(k4_out,   cudaFuncAttributeMaxDynamicSharedMemorySize, k4smem);

    k0_prep<<<BB * LQQ, 256>>>(question, W, bias);
    k1_score<<<dim3(4, BB), 256, k1smem>>>(contex);
    k2c_inv<<<BB, LQQ>>>();
    k3_c2<<<dim3(4, BB), 256, k3smem>>>(contex);
    k4_out<<<dim3(4, BB), 256, k4smem>>>(contex, question, out);
}

// round 9
// speedup vs baseline: 2.8859x; 1.0417x over previous
#include <cuda_runtime.h>
#include <math.h>

#define BB  64
#define LCC 512
#define LQQ 64
#define DD  256

// ---------------------------------------------------------------------------
// tf32 mma (m16n8k8, row.col, fp32 accum) — operands are RAW fp32 bits
// ---------------------------------------------------------------------------
__device__ __forceinline__ void mma8(float& d0, float& d1, float& d2, float& d3,
                                     unsigned a0, unsigned a1, unsigned a2, unsigned a3,
                                     unsigned b0, unsigned b1) {
    asm("mma.sync.aligned.m16n8k8.row.col.f32.tf32.tf32.f32 "
        "{%0,%1,%2,%3},{%4,%5,%6,%7},{%8,%9},{%0,%1,%2,%3};"
        : "+f"(d0), "+f"(d1), "+f"(d2), "+f"(d3)
        : "r"(a0), "r"(a1), "r"(a2), "r"(a3), "r"(b0), "r"(b1));
}
__device__ __forceinline__ unsigned sm2u(const void* p) {
    unsigned r;
    asm("{.reg .u64 t; cvta.to.shared.u64 t, %1; cvt.u32.u64 %0, t;}" : "=r"(r) : "l"(p));
    return r;
}
#define CPA16(dst, src) asm volatile("cp.async.ca.shared.global [%0], [%1], 16;" :: "r"(dst), "l"(src))
#define CPCOMMIT()      asm volatile("cp.async.commit_group;")
#define CPWAIT1()       asm volatile("cp.async.wait_group 1;")
#define CPWAIT0()       asm volatile("cp.async.wait_group 0;")

// Scratch (device globals; no allocation allowed)
__device__ float g_Qp[(size_t)BB * LQQ * DD];            // wi*q + wc
__device__ float g_t[BB * LQQ];                          // <q,wq> + bias
__device__ float g_S1[(size_t)BB * LCC * LQQ];           // row-softmax(S)
__device__ float g_rs[BB * LCC];                         // unshifted row expsums
__device__ float g_cpart[4 * BB * LQQ];                  // per-i-block col expsum partials
__device__ float g_C2[(size_t)BB * LQQ * DD];            // S2^T @ contex

// ---------------------------------------------------------------------------
// K0: Q'[b,j,d] = wi[d]*q[b,j,d] + wc[d];  t[b,j] = <q[b,j], wq> + bias
// ---------------------------------------------------------------------------
__global__ void k0_prep(const float* __restrict__ q,
                        const float* __restrict__ W,
                        const float* __restrict__ bias) {
    const int bj = blockIdx.x;
    const int d  = threadIdx.x;
    const float qv = q[(size_t)bj * DD + d];
    g_Qp[(size_t)bj * DD + d] = fmaf(W[2 * DD + d], qv, W[DD + d]);

    float v = qv * W[d];
    #pragma unroll
    for (int o = 16; o > 0; o >>= 1) v += __shfl_xor_sync(0xffffffffu, v, o);
    __shared__ float red[8];
    if ((threadIdx.x & 31) == 0) red[threadIdx.x >> 5] = v;
    __syncthreads();
    if (threadIdx.x == 0) {
        float s = 0.f;
        #pragma unroll
        for (int i = 0; i < 8; i++) s += red[i];
        g_t[bj] = s + bias[0];
    }
}

// ---------------------------------------------------------------------------
// K1: S = contex @ Q'^T + t via raw-fp32 tf32 mma, 3-stage cp.async pipeline.
// Block 128(i) x 64(j), 256 thr = 8 warps (16x64), K=256. grid=(4, B)
// Outputs: S1 (row softmax), rs (row expsums), col expsum partials.
// ---------------------------------------------------------------------------
__global__ void __launch_bounds__(256, 2) k1_score(const float* __restrict__ contex) {
    const int b  = blockIdx.y;
    const int i0 = blockIdx.x * 128;
    const int tid = threadIdx.x;
    const int warp = tid >> 5, lane = tid & 31;
    const int g = lane >> 2, t = lane & 3;
    const int wm = warp * 16;

    extern __shared__ float sm[];
    float* As   = sm;                 // 3 x 128 x 36 = 13824
    float* Bs   = sm + 13824;         // 3 x 64 x 36  = 6912
    float* ts   = sm + 20736;         // 64
    float* scol = sm + 20800;         // 8 x 64 = 512
    if (tid < 64) ts[tid] = g_t[b * LQQ + tid];

    const float* Cb = contex + (size_t)b * LCC * DD;
    const float* Qp = g_Qp  + (size_t)b * LQQ * DD;

    const int alr = tid >> 1, ako = (tid & 1) * 16;   // A: 4x16B per stage
    const int bjr = tid >> 2, bko = (tid & 3) * 8;    // B: 2x16B per stage
    const unsigned smu = sm2u(sm);

    auto cpStage = [&](int s) {
        const int buf = s % 3;
        const float* ga = &Cb[(size_t)(i0 + alr) * DD + s * 32 + ako];
        unsigned da = smu + (unsigned)((buf * 128 + alr) * 36 + ako) * 4u;
        CPA16(da,      ga);     CPA16(da + 16, ga + 4);
        CPA16(da + 32, ga + 8); CPA16(da + 48, ga + 12);
        const float* gb = &Qp[(size_t)bjr * DD + s * 32 + bko];
        unsigned db = smu + (unsigned)(13824 + (buf * 64 + bjr) * 36 + bko) * 4u;
        CPA16(db, gb); CPA16(db + 16, gb + 4);
        CPCOMMIT();
    };

    float acc[8][4];
    #pragma unroll
    for (int nt = 0; nt < 8; nt++)
        #pragma unroll
        for (int r = 0; r < 4; r++) acc[nt][r] = 0.f;

    cpStage(0); cpStage(1);

    #pragma unroll
    for (int it = 0; it < 8; it++) {
        if (it < 7) { CPWAIT1(); } else { CPWAIT0(); }
        __syncthreads();
        if (it + 2 < 8) cpStage(it + 2);
        const float* Ab = As + (size_t)(it % 3) * 128 * 36;
        const float* Bb = Bs + (size_t)(it % 3) * 64 * 36;
        #pragma unroll
        for (int kc = 0; kc < 32; kc += 8) {
            unsigned a0 = *(const unsigned*)&Ab[(size_t)(wm + g) * 36 + kc + t];
            unsigned a1 = *(const unsigned*)&Ab[(size_t)(wm + 8 + g) * 36 + kc + t];
            unsigned a2 = *(const unsigned*)&Ab[(size_t)(wm + g) * 36 + kc + t + 4];
            unsigned a3 = *(const unsigned*)&Ab[(size_t)(wm + 8 + g) * 36 + kc + t + 4];
            #pragma unroll
            for (int nt = 0; nt < 8; nt++) {
                unsigned b0 = *(const unsigned*)&Bb[(size_t)(nt * 8 + g) * 36 + kc + t];
                unsigned b1 = *(const unsigned*)&Bb[(size_t)(nt * 8 + g) * 36 + kc + t + 4];
                mma8(acc[nt][0], acc[nt][1], acc[nt][2], acc[nt][3],
                     a0, a1, a2, a3, b0, b1);
            }
        }
        __syncthreads();
    }

    // ---- epilogue: +t[j], col expsums, row softmax -> S1, row sums -> rs ----
    float* S1b = g_S1 + (size_t)b * LCC * LQQ;
    float cs[16];
    #pragma unroll
    for (int c = 0; c < 16; c++) cs[c] = 0.f;

    #pragma unroll
    for (int h = 0; h < 2; h++) {
        const int i = i0 + wm + h * 8 + g;
        float s[16];
        #pragma unroll
        for (int nt = 0; nt < 8; nt++) {
            s[2 * nt]     = acc[nt][2 * h]     + ts[nt * 8 + 2 * t];
            s[2 * nt + 1] = acc[nt][2 * h + 1] + ts[nt * 8 + 2 * t + 1];
        }
        #pragma unroll
        for (int c = 0; c < 16; c++) cs[c] += __expf(s[c]);
        float m = s[0];
        #pragma unroll
        for (int c = 1; c < 16; c++) m = fmaxf(m, s[c]);
        m = fmaxf(m, __shfl_xor_sync(0xffffffffu, m, 1));
        m = fmaxf(m, __shfl_xor_sync(0xffffffffu, m, 2));
        float e[16], sum = 0.f;
        #pragma unroll
        for (int c = 0; c < 16; c++) { e[c] = __expf(s[c] - m); sum += e[c]; }
        sum += __shfl_xor_sync(0xffffffffu, sum, 1);
        sum += __shfl_xor_sync(0xffffffffu, sum, 2);
        const float inv = 1.f / sum;
        #pragma unroll
        for (int nt = 0; nt < 8; nt++) {
            float2 o = make_float2(e[2 * nt] * inv, e[2 * nt + 1] * inv);
            *(float2*)&S1b[(size_t)i * LQQ + nt * 8 + 2 * t] = o;
        }
        if (t == 0) g_rs[b * LCC + i] = sum * __expf(m);
    }
    #pragma unroll
    for (int c = 0; c < 16; c++) {
        cs[c] += __shfl_xor_sync(0xffffffffu, cs[c], 4);
        cs[c] += __shfl_xor_sync(0xffffffffu, cs[c], 8);
        cs[c] += __shfl_xor_sync(0xffffffffu, cs[c], 16);
    }
    if (g == 0) {
        #pragma unroll
        for (int c = 0; c < 16; c++) {
            const int j = (c >> 1) * 8 + 2 * t + (c & 1);
            scol[warp * 64 + j] = cs[c];
        }
    }
    __syncthreads();
    if (tid < 64) {
        float p = 0.f;
        #pragma unroll
        for (int w = 0; w < 8; w++) p += scol[w * 64 + tid];
        g_cpart[blockIdx.x * (BB * LQQ) + b * LQQ + tid] = p;
    }
}

// ---------------------------------------------------------------------------
// K3: C2 = S2^T @ contex, full K=512.  S2[i,j] = S1[i,j]*rs_i*inv_j built on
// the A-fill from L2-hot S1 (no exp).  inv combine folded into prologue.
// Block 64(j) x 64(n), 512 thr = 16 warps 4(m)x4(n), warp tile 16x16.
// A stored [k][j] so the transpose-fill is one float4 STS. grid=(4, B)
// ---------------------------------------------------------------------------
__global__ void __launch_bounds__(512, 2) k3_c2(const float* __restrict__ contex) {
    const int b   = blockIdx.y;
    const int n0  = blockIdx.x * 64;
    const int tid = threadIdx.x;
    const int warp = tid >> 5, lane = tid & 31;
    const int g = lane >> 2, t = lane & 3;
    const int wm = (warp & 3) * 16;
    const int wn = (warp >> 2) * 16;

    extern __shared__ float sm3[];
    float* As   = sm3;                     // 2 x 32 x 68 [k=i][j]
    float* Bs   = sm3 + 4352;              // 3 x 32 x 72 [k][n]
    float* rssm = sm3 + 4352 + 6912;       // 512
    float* sinv = rssm + 512;              // 64

    const float* S1b = g_S1 + (size_t)b * LCC * LQQ;
    const float* Cb  = contex + (size_t)b * LCC * DD;

    rssm[tid] = g_rs[b * LCC + tid];
    if (tid < 64) {
        const int idx = b * LQQ + tid;
        float s = g_cpart[idx] + g_cpart[BB * LQQ + idx]
                + g_cpart[2 * BB * LQQ + idx] + g_cpart[3 * BB * LQQ + idx];
        sinv[tid] = 1.f / s;
    }
    __syncthreads();

    const int iloc = tid >> 4, jo = (tid & 15) * 4;   // A fill: 32 rows x 64 j
    const float4 inv4 = *(const float4*)&sinv[jo];
    const unsigned smu = sm2u(sm3);

    auto cpB = [&](int s) {
        const int buf = s % 3;
        const float* c = &Cb[(size_t)(s * 32 + iloc) * DD + n0 + jo];
        unsigned db = smu + (unsigned)(4352 + (buf * 32 + iloc) * 72 + jo) * 4u;
        CPA16(db, c);
        CPCOMMIT();
    };

    float4 ra; float rsv;
    auto ldA = [&](int s) {
        ra  = *(const float4*)&S1b[(size_t)(s * 32 + iloc) * LQQ + jo];
        rsv = rssm[s * 32 + iloc];
    };
    auto stA = [&](int s) {
        float4 v = make_float4(ra.x * rsv * inv4.x, ra.y * rsv * inv4.y,
                               ra.z * rsv * inv4.z, ra.w * rsv * inv4.w);
        *(float4*)&As[(size_t)((s & 1) * 32 + iloc) * 68 + jo] = v;
    };

    float acc[2][4];
    #pragma unroll
    for (int nt = 0; nt < 2; nt++)
        #pragma unroll
        for (int r = 0; r < 4; r++) acc[nt][r] = 0.f;

    cpB(0); cpB(1);
    ldA(0); stA(0);

    #pragma unroll 4
    for (int it = 0; it < 16; it++) {
        if (it < 15) { CPWAIT1(); } else { CPWAIT0(); }
        __syncthreads();
        if (it + 2 < 16) cpB(it + 2);
        if (it < 15) ldA(it + 1);

        const float* Ab = As + (size_t)(it & 1) * 32 * 68;
        const float* Bb = Bs + (size_t)(it % 3) * 32 * 72;
        #pragma unroll
        for (int kc = 0; kc < 32; kc += 8) {
            unsigned a0 = *(const unsigned*)&Ab[(size_t)(kc + t) * 68 + wm + g];
            unsigned a1 = *(const unsigned*)&Ab[(size_t)(kc + t) * 68 + wm + 8 + g];
            unsigned a2 = *(const unsigned*)&Ab[(size_t)(kc + t + 4) * 68 + wm + g];
            unsigned a3 = *(const unsigned*)&Ab[(size_t)(kc + t + 4) * 68 + wm + 8 + g];
            #pragma unroll
            for (int nt = 0; nt < 2; nt++) {
                const int n = wn + nt * 8 + g;
                unsigned b0 = *(const unsigned*)&Bb[(size_t)(kc + t) * 72 + n];
                unsigned b1 = *(const unsigned*)&Bb[(size_t)(kc + t + 4) * 72 + n];
                mma8(acc[nt][0], acc[nt][1], acc[nt][2], acc[nt][3],
                     a0, a1, a2, a3, b0, b1);
            }
        }
        if (it < 15) stA(it + 1);
        __syncthreads();
    }

    float* outp = g_C2 + (size_t)b * LQQ * DD;
    #pragma unroll
    for (int h = 0; h < 2; h++) {
        const int j = wm + h * 8 + g;
        #pragma unroll
        for (int nt = 0; nt < 2; nt++) {
            float2 o = make_float2(acc[nt][2 * h], acc[nt][2 * h + 1]);
            *(float2*)&outp[(size_t)j * DD + n0 + wn + nt * 8 + 2 * t] = o;
        }
    }
}

// ---------------------------------------------------------------------------
// K4: A = S1 @ question, Bm = S1 @ C2, dual-B per chunk (4 chunks),
// fused output: out[b,i] = [contex | A | contex*A | contex*Bm]
// Block 128(i), 256 thr = 8 warps (16x64). Raw fp32 operands. grid=(4, B)
// ---------------------------------------------------------------------------
__global__ void __launch_bounds__(256) k4_out(const float* __restrict__ contex,
                                              const float* __restrict__ question,
                                              float* __restrict__ out) {
    const int b  = blockIdx.y;
    const int i0 = blockIdx.x * 128;
    const int tid = threadIdx.x;
    const int warp = tid >> 5, lane = tid & 31;
    const int g = lane >> 2, t = lane & 3;
    const int wm = warp * 16;

    extern __shared__ float sm4[];
    float* As = sm4;                        // 128 x 68 [i][j] persistent
    float* Bt = sm4 + 128 * 68;             // 2 buf x 2 tiles x 64 x 72

    const float* S1b = g_S1 + (size_t)b * LCC * LQQ;
    {   // fill A once (raw fp32)
        const int lr = tid >> 1, jo = (tid & 1) * 32;
        const float* src = &S1b[(size_t)(i0 + lr) * LQQ + jo];
        float* dst = &As[(size_t)lr * 68 + jo];
        #pragma unroll
        for (int u = 0; u < 8; u++) *(float4*)&dst[u * 4] = *(const float4*)&src[u * 4];
    }

    const float* Cb = contex   + (size_t)b * LCC * DD;
    const float* Qb = question + (size_t)b * LQQ * DD;
    const float* P  = g_C2     + (size_t)b * LQQ * DD;
    float* outb = out + (size_t)b * LCC * 1024;

    const int bjr = tid >> 2, boff = (tid & 3) * 16;
    float4 rq[4], rc[4];

    auto ldB = [&](int chunk) {
        const int c0 = chunk * 64;
        const float* src = &Qb[(size_t)bjr * DD + c0 + boff];
        rq[0] = *(const float4*)&src[0];  rq[1] = *(const float4*)&src[4];
        rq[2] = *(const float4*)&src[8];  rq[3] = *(const float4*)&src[12];
        const float* s0 = &P[(size_t)bjr * DD + c0 + boff];
        rc[0] = *(const float4*)&s0[0];  rc[1] = *(const float4*)&s0[4];
        rc[2] = *(const float4*)&s0[8];  rc[3] = *(const float4*)&s0[12];
    };
    auto stB = [&](int buf) {
        float* dq = &Bt[((size_t)buf * 128 + bjr) * 72 + boff];
        *(float4*)&dq[0] = rq[0]; *(float4*)&dq[4] = rq[1];
        *(float4*)&dq[8] = rq[2]; *(float4*)&dq[12] = rq[3];
        float* dc = &Bt[((size_t)buf * 128 + 64 + bjr) * 72 + boff];
        *(float4*)&dc[0] = rc[0]; *(float4*)&dc[4] = rc[1];
        *(float4*)&dc[8] = rc[2]; *(float4*)&dc[12] = rc[3];
    };

    ldB(0); stB(0);
    __syncthreads();

    #pragma unroll
    for (int chunk = 0; chunk < 4; chunk++) {
        const int buf = chunk & 1;
        const int c0 = chunk * 64;
        if (chunk < 3) ldB(chunk + 1);

        float accq[8][4], accc[8][4];
        #pragma unroll
        for (int nt = 0; nt < 8; nt++)
            #pragma unroll
            for (int r = 0; r < 4; r++) { accq[nt][r] = 0.f; accc[nt][r] = 0.f; }

        const float* Bq = Bt + (size_t)buf * 128 * 72;
        const float* Bc = Bq + 64 * 72;
        #pragma unroll
        for (int kc = 0; kc < 64; kc += 8) {
            unsigned a0 = *(const unsigned*)&As[(size_t)(wm + g) * 68 + kc + t];
            unsigned a1 = *(const unsigned*)&As[(size_t)(wm + 8 + g) * 68 + kc + t];
            unsigned a2 = *(const unsigned*)&As[(size_t)(wm + g) * 68 + kc + t + 4];
            unsigned a3 = *(const unsigned*)&As[(size_t)(wm + 8 + g) * 68 + kc + t + 4];
            #pragma unroll
            for (int nt = 0; nt < 8; nt++) {
                const int n = nt * 8 + g;
                unsigned q0 = *(const unsigned*)&Bq[(size_t)(kc + t) * 72 + n];
                unsigned q1 = *(const unsigned*)&Bq[(size_t)(kc + t + 4) * 72 + n];
                mma8(accq[nt][0], accq[nt][1], accq[nt][2], accq[nt][3],
                     a0, a1, a2, a3, q0, q1);
                unsigned c0r = *(const unsigned*)&Bc[(size_t)(kc + t) * 72 + n];
                unsigned c1r = *(const unsigned*)&Bc[(size_t)(kc + t + 4) * 72 + n];
                mma8(accc[nt][0], accc[nt][1], accc[nt][2], accc[nt][3],
                     a0, a1, a2, a3, c0r, c1r);
            }
        }

        #pragma unroll
        for (int h = 0; h < 2; h++) {
            const int i = i0 + wm + h * 8 + g;
            const float* crow = &Cb[(size_t)i * DD];
            float* orow = &outb[(size_t)i * 1024];
            #pragma unroll
            for (int nt = 0; nt < 8; nt++) {
                const int col = c0 + nt * 8 + 2 * t;
                float2 cv = *(const float2*)&crow[col];
                float2 av = make_float2(accq[nt][2 * h], accq[nt][2 * h + 1]);
                float2 bv = make_float2(accc[nt][2 * h], accc[nt][2 * h + 1]);
                float2 pa = make_float2(cv.x * av.x, cv.y * av.y);
                float2 pb = make_float2(cv.x * bv.x, cv.y * bv.y);
                *(float2*)&orow[col]       = cv;
                *(float2*)&orow[256 + col] = av;
                *(float2*)&orow[512 + col] = pa;
                *(float2*)&orow[768 + col] = pb;
            }
        }

        if (chunk < 3) stB(buf ^ 1);
        __syncthreads();
    }
}

// ---------------------------------------------------------------------------
extern "C" void kernel_launch(void* const* d_in, const int* in_sizes, int n_in,
                              void* d_out, int out_size) {
    const float* contex   = (const float*)d_in[0];
    const float* question = (const float*)d_in[1];
    const float* W        = (const float*)d_in[2];
    const float* bias     = (const float*)d_in[3];
    float* out = (float*)d_out;

    const int k1smem = 21312 * (int)sizeof(float);                          // 85248
    const int k3smem = (4352 + 6912 + 512 + 64) * (int)sizeof(float);       // 47360
    const int k4smem = (128 * 68 + 2 * 2 * 64 * 72) * (int)sizeof(float);   // 108544
    cudaFuncSetAttribute(k1_score, cudaFuncAttributeMaxDynamicSharedMemorySize, k1smem);
    cudaFuncSetAttribute(k3_c2,    cudaFuncAttributeMaxDynamicSharedMemorySize, k3smem);
    cudaFuncSetAttribute(k4_out,   cudaFuncAttributeMaxDynamicSharedMemorySize, k4smem);

    k0_prep<<<BB * LQQ, 256>>>(question, W, bias);
    k1_score<<<dim3(4, BB), 256, k1smem>>>(contex);
    k3_c2<<<dim3(4, BB), 512, k3smem>>>(contex);
    k4_out<<<dim3(4, BB), 256, k4smem>>>(contex, question, out);
}